// round 3
// baseline (speedup 1.0000x reference)
#include <cuda_runtime.h>
#include <cuda_bf16.h>
#include <cstdint>

#define NN   50000
#define EE   800000
#define ETOT (EE + NN)     // edges + self loops = 850000
#define DHx  128
#define DOUTx 64
#define NGx  128

// ---------------- device scratch (globals; no allocation allowed) ----------------
__device__ int   g_is64;             // 1 if edge_index is int64, 0 if int32
__device__ int   g_cnt[NN];
__device__ int   g_btot[64];
__device__ int   g_boff[64];
__device__ int   g_rowptr[NN + 1];
__device__ int   g_cur[NN];
__device__ int   g_ssrc[ETOT];
__device__ float g_xp[NN * DHx];     // GEMM output (layer3 uses first NN*64)
__device__ float g_h [NN * DHx];     // GAT layer output (layers 1-2)
__device__ float g_ha[NN * DHx];     // activated (BN+ReLU) buffer
__device__ float g_es[NN];
__device__ float g_ed[NN];
__device__ float g_stats[2 * DHx];   // colsum, colsumsq
__device__ float g_scale[DHx];
__device__ float g_shift[DHx];
__device__ float g_pool[NGx * DOUTx];

// ---------------- edge dtype detection ----------------
// int64 values < 2^31 -> odd 32-bit words are all zero. int32 edge ids -> mostly nonzero.
__global__ void k_detect(const unsigned int* __restrict__ ei_raw) {
    __shared__ unsigned int sh[256];
    int t = threadIdx.x;
    unsigned int v = 0;
    for (int i = t; i < 1024; i += 256) v |= ei_raw[2 * i + 1];
    sh[t] = v;
    __syncthreads();
    for (int off = 128; off; off >>= 1) {
        if (t < off) sh[t] |= sh[t + off];
        __syncthreads();
    }
    if (t == 0) g_is64 = (sh[0] == 0) ? 1 : 0;
}

__device__ __forceinline__ int edge_at(const void* ei, int idx) {
    int v;
    if (g_is64) v = (int)((const long long*)ei)[idx];
    else        v = ((const int*)ei)[idx];
    // defensive clamp: if dtype detection is ever wrong we get a numeric
    // mismatch (diagnosable) instead of a device trap.
    v = v < 0 ? 0 : (v >= NN ? NN - 1 : v);
    return v;
}

// ---------------- CSR build ----------------
__global__ void k_zero_cnt() {
    int i = blockIdx.x * blockDim.x + threadIdx.x;
    if (i < NN) g_cnt[i] = 0;
}

__global__ void k_hist(const void* __restrict__ ei) {
    int e = blockIdx.x * blockDim.x + threadIdx.x;
    if (e >= ETOT) return;
    int dst = (e < EE) ? edge_at(ei, EE + e) : (e - EE);
    atomicAdd(&g_cnt[dst], 1);
}

__global__ void k_scan1() {   // 49 blocks x 1024: blockwise exclusive scan (in-place) + block totals
    int t = threadIdx.x;
    int i = blockIdx.x * 1024 + t;
    int v = (i < NN) ? g_cnt[i] : 0;
    __shared__ int sh[1024];
    sh[t] = v;
    __syncthreads();
    for (int off = 1; off < 1024; off <<= 1) {
        int a = (t >= off) ? sh[t - off] : 0;
        __syncthreads();
        sh[t] += a;
        __syncthreads();
    }
    if (i < NN) g_cnt[i] = sh[t] - v;           // exclusive
    if (t == 1023) g_btot[blockIdx.x] = sh[1023];
}

__global__ void k_scan2() {   // 1 block x 64: exclusive scan of block totals
    int t = threadIdx.x;
    int v = (t < 49) ? g_btot[t] : 0;
    __shared__ int sh[64];
    sh[t] = v;
    __syncthreads();
    for (int off = 1; off < 64; off <<= 1) {
        int a = (t >= off) ? sh[t - off] : 0;
        __syncthreads();
        sh[t] += a;
        __syncthreads();
    }
    if (t < 49) g_boff[t] = sh[t] - v;
}

__global__ void k_scan3() {
    int i = blockIdx.x * 1024 + threadIdx.x;
    if (i < NN) {
        int rp = g_cnt[i] + g_boff[blockIdx.x];
        g_rowptr[i] = rp;
        g_cur[i] = rp;
    }
    if (i == 0) g_rowptr[NN] = ETOT;
}

__global__ void k_scatter(const void* __restrict__ ei) {
    int e = blockIdx.x * blockDim.x + threadIdx.x;
    if (e >= ETOT) return;
    int s, d;
    if (e < EE) { s = edge_at(ei, e); d = edge_at(ei, EE + e); }
    else        { s = e - EE;         d = s; }
    int pos = atomicAdd(&g_cur[d], 1);
    g_ssrc[pos] = s;
}

// ---------------- GEMM: g_xp[n,NOUT] = A[n,128] @ W[128,NOUT] ----------------
// A == nullptr -> use g_ha as input
template <int NOUT>
__global__ void k_gemm(const float* __restrict__ A, const float* __restrict__ W, int n) {
    const float* __restrict__ Ap = A ? A : (const float*)g_ha;
    constexpr int TN = NOUT / 16;
    __shared__ float As[16][65];      // [k][m], padded
    __shared__ float Ws[16][NOUT];    // [k][c]
    int tid = threadIdx.x;
    int tx = tid & 15, ty = tid >> 4;
    int r0 = blockIdx.x * 64;

    float acc[4][TN];
#pragma unroll
    for (int j = 0; j < 4; j++)
#pragma unroll
        for (int t = 0; t < TN; t++) acc[j][t] = 0.f;

    int ar = tid >> 2;          // 0..63 row within tile
    int kq = (tid & 3) * 4;     // k sub offset

    for (int k0 = 0; k0 < 128; k0 += 16) {
        float a0 = 0.f, a1 = 0.f, a2 = 0.f, a3 = 0.f;
        if (r0 + ar < n) {
            const float* p = &Ap[(r0 + ar) * 128 + k0 + kq];
            a0 = p[0]; a1 = p[1]; a2 = p[2]; a3 = p[3];
        }
        As[kq + 0][ar] = a0; As[kq + 1][ar] = a1;
        As[kq + 2][ar] = a2; As[kq + 3][ar] = a3;

        for (int l = tid; l < 16 * NOUT; l += 256) {
            int kk = l / NOUT;
            int cc = l % NOUT;
            Ws[kk][cc] = W[(k0 + kk) * NOUT + cc];
        }
        __syncthreads();

#pragma unroll
        for (int kk = 0; kk < 16; kk++) {
            float v0 = As[kk][ty * 4 + 0];
            float v1 = As[kk][ty * 4 + 1];
            float v2 = As[kk][ty * 4 + 2];
            float v3 = As[kk][ty * 4 + 3];
            float wv[TN];
#pragma unroll
            for (int t = 0; t < TN; t++) wv[t] = Ws[kk][tx * TN + t];
#pragma unroll
            for (int t = 0; t < TN; t++) {
                acc[0][t] += v0 * wv[t];
                acc[1][t] += v1 * wv[t];
                acc[2][t] += v2 * wv[t];
                acc[3][t] += v3 * wv[t];
            }
        }
        __syncthreads();
    }

#pragma unroll
    for (int j = 0; j < 4; j++) {
        int r = r0 + ty * 4 + j;
        if (r < n) {
#pragma unroll
            for (int t = 0; t < TN; t++)
                g_xp[r * NOUT + tx * TN + t] = acc[j][t];
        }
    }
}

// ---------------- attention dot products: e_src/e_dst per node ----------------
template <int C>
__global__ void k_edots(const float* __restrict__ asv, const float* __restrict__ adv, int n) {
    int w = (blockIdx.x * blockDim.x + threadIdx.x) >> 5;
    int lane = threadIdx.x & 31;
    if (w >= n) return;
    float s1 = 0.f, s2 = 0.f;
#pragma unroll
    for (int c = lane; c < C; c += 32) {
        float v = g_xp[w * C + c];
        s1 += v * asv[c];
        s2 += v * adv[c];
    }
#pragma unroll
    for (int off = 16; off; off >>= 1) {
        s1 += __shfl_down_sync(0xffffffffu, s1, off);
        s2 += __shfl_down_sync(0xffffffffu, s2, off);
    }
    if (lane == 0) { g_es[w] = s1; g_ed[w] = s2; }
}

// ---------------- GAT aggregation: one block per destination node ----------------
// out == nullptr -> write to g_h
template <int C>
__global__ void k_agg(const float* __restrict__ bias, float* __restrict__ out) {
    float* __restrict__ outp = out ? out : (float*)g_h;
    int i   = blockIdx.x;
    int tid = threadIdx.x;
    int beg = g_rowptr[i], end = g_rowptr[i + 1];
    float edv = g_ed[i];

    __shared__ float ws[C];
    __shared__ int   ss[C];
    __shared__ float red[C];

    // pass 1: segment max of leaky(al)
    float m = -3.4e38f;
    for (int p = beg + tid; p < end; p += C) {
        float al = g_es[g_ssrc[p]] + edv;
        al = al > 0.f ? al : 0.2f * al;
        m = fmaxf(m, al);
    }
    red[tid] = m; __syncthreads();
#pragma unroll
    for (int off = C / 2; off; off >>= 1) {
        if (tid < off) red[tid] = fmaxf(red[tid], red[tid + off]);
        __syncthreads();
    }
    m = red[0];
    __syncthreads();

    // pass 2: weights + weighted gather accumulate
    float acc = 0.f, dp = 0.f;
    for (int base = beg; base < end; base += C) {
        int p = base + tid;
        float w = 0.f; int s = 0;
        if (p < end) {
            s = g_ssrc[p];
            float al = g_es[s] + edv;
            al = al > 0.f ? al : 0.2f * al;
            w = __expf(al - m);
        }
        ws[tid] = w; ss[tid] = s; dp += w;
        __syncthreads();
        int cnt = min(C, end - base);
        for (int j = 0; j < cnt; j++)
            acc += ws[j] * g_xp[ss[j] * C + tid];
        __syncthreads();
    }

    red[tid] = dp; __syncthreads();
#pragma unroll
    for (int off = C / 2; off; off >>= 1) {
        if (tid < off) red[tid] += red[tid + off];
        __syncthreads();
    }
    float den = red[0];
    outp[i * C + tid] = acc / den + bias[tid];
}

// ---------------- BatchNorm ----------------
__global__ void k_zero_stats() {
    int i = threadIdx.x;
    if (i < 2 * DHx) g_stats[i] = 0.f;
}

__global__ void k_bnstats(int n) {
    int c = threadIdx.x;     // 128 threads
    float s = 0.f, sq = 0.f;
    for (int r = blockIdx.x; r < n; r += gridDim.x) {
        float v = g_h[r * 128 + c];
        s += v; sq += v * v;
    }
    atomicAdd(&g_stats[c], s);
    atomicAdd(&g_stats[128 + c], sq);
}

__global__ void k_bnparams(const float* __restrict__ g, const float* __restrict__ be, int n) {
    int c = threadIdx.x;     // 128
    float inv_n = 1.f / (float)n;
    float m = g_stats[c] * inv_n;
    float v = g_stats[128 + c] * inv_n - m * m;
    float sc = g[c] * rsqrtf(v + 1e-5f);
    g_scale[c] = sc;
    g_shift[c] = be[c] - m * sc;
}

__global__ void k_bnapply(int n) {   // g_h -> g_ha, relu(bn(h))
    int i = blockIdx.x * blockDim.x + threadIdx.x;
    if (i >= n * 128) return;
    int c = i & 127;
    float v = g_h[i] * g_scale[c] + g_shift[c];
    g_ha[i] = v > 0.f ? v : 0.f;
}

// ---------------- pooling: g_pool[128,64] = gp[128,n] @ hn[n,64] ----------------
__global__ void k_zero_pool() {
    int i = blockIdx.x * blockDim.x + threadIdx.x;
    if (i < NGx * DOUTx) g_pool[i] = 0.f;
}

__global__ void k_pool(const float* __restrict__ gp, const float* __restrict__ hn, int n) {
    __shared__ float gpt[32][129];   // [k][m] padded
    __shared__ float hnt[32][65];    // [k][c] padded
    int tid = threadIdx.x;
    int tn = (tid & 15) * 4;
    int tm = (tid >> 4) * 8;
    float acc[8][4];
#pragma unroll
    for (int a = 0; a < 8; a++)
#pragma unroll
        for (int b = 0; b < 4; b++) acc[a][b] = 0.f;

    int kpb  = (n + gridDim.x - 1) / gridDim.x;
    int kbeg = blockIdx.x * kpb;
    int kend = min(n, kbeg + kpb);

    for (int k0 = kbeg; k0 < kend; k0 += 32) {
        int kt = min(32, kend - k0);
        for (int l = tid; l < 128 * 32; l += 256) {
            int m = l >> 5, kk = l & 31;
            gpt[kk][m] = (kk < kt) ? gp[m * n + k0 + kk] : 0.f;
        }
        for (int l = tid; l < 32 * 64; l += 256) {
            int kk = l >> 6, cc = l & 63;
            hnt[kk][cc] = (kk < kt) ? hn[(k0 + kk) * 64 + cc] : 0.f;
        }
        __syncthreads();
#pragma unroll 4
        for (int kk = 0; kk < 32; kk++) {
            float h0 = hnt[kk][tn + 0], h1 = hnt[kk][tn + 1];
            float h2 = hnt[kk][tn + 2], h3 = hnt[kk][tn + 3];
#pragma unroll
            for (int a = 0; a < 8; a++) {
                float g = gpt[kk][tm + a];
                acc[a][0] += g * h0;
                acc[a][1] += g * h1;
                acc[a][2] += g * h2;
                acc[a][3] += g * h3;
            }
        }
        __syncthreads();
    }
#pragma unroll
    for (int a = 0; a < 8; a++)
#pragma unroll
        for (int b = 0; b < 4; b++)
            atomicAdd(&g_pool[(tm + a) * 64 + tn + b], acc[a][b]);
}

__global__ void k_copy_pool(float* __restrict__ out) {
    int i = blockIdx.x * blockDim.x + threadIdx.x;
    if (i < NGx * DOUTx) out[i] = g_pool[i];
}

// ---------------- launch ----------------
extern "C" void kernel_launch(void* const* d_in, const int* in_sizes, int n_in,
                              void* d_out, int out_size) {
    const float* x   = (const float*)d_in[0];
    const void*  ei  = (const void*)d_in[1];
    const float* gp  = (const float*)d_in[2];
    const float* W1  = (const float*)d_in[3];
    const float* as1 = (const float*)d_in[4];
    const float* ad1 = (const float*)d_in[5];
    const float* b1  = (const float*)d_in[6];
    const float* g1  = (const float*)d_in[7];
    const float* be1 = (const float*)d_in[8];
    const float* W2  = (const float*)d_in[9];
    const float* as2 = (const float*)d_in[10];
    const float* ad2 = (const float*)d_in[11];
    const float* b2  = (const float*)d_in[12];
    const float* g2  = (const float*)d_in[13];
    const float* be2 = (const float*)d_in[14];
    const float* W3  = (const float*)d_in[15];
    const float* as3 = (const float*)d_in[16];
    const float* ad3 = (const float*)d_in[17];
    const float* b3  = (const float*)d_in[18];

    float* out       = (float*)d_out;
    float* out_pool  = out;                    // [128,64]
    float* out_nodes = out + NGx * DOUTx;      // [50000,64]

    const int T = 256;

    // edge dtype sniff (int32 vs int64)
    k_detect<<<1, 256>>>((const unsigned int*)ei);

    // CSR by destination (graph structure, shared by all 3 layers)
    k_zero_cnt<<<(NN + T - 1) / T, T>>>();
    k_hist<<<(ETOT + T - 1) / T, T>>>(ei);
    k_scan1<<<49, 1024>>>();
    k_scan2<<<1, 64>>>();
    k_scan3<<<49, 1024>>>();
    k_scatter<<<(ETOT + T - 1) / T, T>>>(ei);

    int gemm_blocks = (NN + 63) / 64;
    int edot_blocks = (NN * 32 + T - 1) / T;

    // ---- Layer 1 ----
    k_gemm<128><<<gemm_blocks, 256>>>(x, W1, NN);
    k_edots<128><<<edot_blocks, T>>>(as1, ad1, NN);
    k_agg<128><<<NN, 128>>>(b1, nullptr);
    k_zero_stats<<<1, 256>>>();
    k_bnstats<<<512, 128>>>(NN);
    k_bnparams<<<1, 128>>>(g1, be1, NN);
    k_bnapply<<<(NN * 128 + T - 1) / T, T>>>(NN);

    // ---- Layer 2 ----
    k_gemm<128><<<gemm_blocks, 256>>>(nullptr, W2, NN);
    k_edots<128><<<edot_blocks, T>>>(as2, ad2, NN);
    k_agg<128><<<NN, 128>>>(b2, nullptr);
    k_zero_stats<<<1, 256>>>();
    k_bnstats<<<512, 128>>>(NN);
    k_bnparams<<<1, 128>>>(g2, be2, NN);
    k_bnapply<<<(NN * 128 + T - 1) / T, T>>>(NN);

    // ---- Layer 3 (64 out channels, no BN) ----
    k_gemm<64><<<gemm_blocks, 256>>>(nullptr, W3, NN);
    k_edots<64><<<edot_blocks, T>>>(as3, ad3, NN);
    k_agg<64><<<NN, 64>>>(b3, out_nodes);

    // ---- pooling ----
    k_zero_pool<<<(NGx * DOUTx + T - 1) / T, T>>>();
    k_pool<<<128, 256>>>(gp, out_nodes, NN);
    k_copy_pool<<<(NGx * DOUTx + T - 1) / T, T>>>(out_pool);
}

// round 4
// speedup vs baseline: 1.4732x; 1.4732x over previous
#include <cuda_runtime.h>
#include <cuda_bf16.h>
#include <cstdint>

#define NN   50000
#define EE   800000
#define ETOT (EE + NN)     // edges + self loops = 850000
#define DHx  128
#define DOUTx 64
#define NGx  128

// ---------------- device scratch ----------------
__device__ int   g_is64;
__device__ int   g_cnt[NN];
__device__ int   g_btot[64];
__device__ int   g_boff[64];
__device__ int   g_rowptr[NN + 1];
__device__ int   g_cur[NN];
__device__ int   g_ssrc[ETOT];
__device__ float g_xp[NN * DHx];     // GEMM output (layer3 uses first NN*64)
__device__ float g_h [NN * DHx];     // GAT layer output (layers 1-2)
__device__ float g_es[NN];
__device__ float g_ed[NN];
__device__ float g_stats[2 * DHx];
__device__ float g_scale[DHx];
__device__ float g_shift[DHx];
__device__ float g_pool[NGx * DOUTx];

// ---------------- edge dtype detection ----------------
__global__ void k_detect(const unsigned int* __restrict__ ei_raw) {
    __shared__ unsigned int sh[256];
    int t = threadIdx.x;
    unsigned int v = 0;
    for (int i = t; i < 1024; i += 256) v |= ei_raw[2 * i + 1];
    sh[t] = v;
    __syncthreads();
    for (int off = 128; off; off >>= 1) {
        if (t < off) sh[t] |= sh[t + off];
        __syncthreads();
    }
    if (t == 0) g_is64 = (sh[0] == 0) ? 1 : 0;
}

__device__ __forceinline__ int edge_at(const void* ei, int idx) {
    int v;
    if (g_is64) v = (int)((const long long*)ei)[idx];
    else        v = ((const int*)ei)[idx];
    v = v < 0 ? 0 : (v >= NN ? NN - 1 : v);
    return v;
}

// ---------------- CSR build ----------------
__global__ void k_zero_cnt() {
    int i = blockIdx.x * blockDim.x + threadIdx.x;
    if (i < NN) g_cnt[i] = 0;
}

__global__ void k_hist(const void* __restrict__ ei) {
    int e = blockIdx.x * blockDim.x + threadIdx.x;
    if (e >= ETOT) return;
    int dst = (e < EE) ? edge_at(ei, EE + e) : (e - EE);
    atomicAdd(&g_cnt[dst], 1);
}

__global__ void k_scan1() {
    int t = threadIdx.x;
    int i = blockIdx.x * 1024 + t;
    int v = (i < NN) ? g_cnt[i] : 0;
    __shared__ int sh[1024];
    sh[t] = v;
    __syncthreads();
    for (int off = 1; off < 1024; off <<= 1) {
        int a = (t >= off) ? sh[t - off] : 0;
        __syncthreads();
        sh[t] += a;
        __syncthreads();
    }
    if (i < NN) g_cnt[i] = sh[t] - v;
    if (t == 1023) g_btot[blockIdx.x] = sh[1023];
}

__global__ void k_scan2() {
    int t = threadIdx.x;
    int v = (t < 49) ? g_btot[t] : 0;
    __shared__ int sh[64];
    sh[t] = v;
    __syncthreads();
    for (int off = 1; off < 64; off <<= 1) {
        int a = (t >= off) ? sh[t - off] : 0;
        __syncthreads();
        sh[t] += a;
        __syncthreads();
    }
    if (t < 49) g_boff[t] = sh[t] - v;
}

__global__ void k_scan3() {
    int i = blockIdx.x * 1024 + threadIdx.x;
    if (i < NN) {
        int rp = g_cnt[i] + g_boff[blockIdx.x];
        g_rowptr[i] = rp;
        g_cur[i] = rp;
    }
    if (i == 0) g_rowptr[NN] = ETOT;
}

__global__ void k_scatter(const void* __restrict__ ei) {
    int e = blockIdx.x * blockDim.x + threadIdx.x;
    if (e >= ETOT) return;
    int s, d;
    if (e < EE) { s = edge_at(ei, e); d = edge_at(ei, EE + e); }
    else        { s = e - EE;         d = s; }
    int pos = atomicAdd(&g_cur[d], 1);
    g_ssrc[pos] = s;
}

// ---------------- GEMM: g_xp[n,NOUT] = act(A)[n,128] @ W[128,NOUT] ----------------
// BN=true: A = relu(g_h * g_scale + g_shift) computed on load (A ptr ignored, uses g_h)
template <int NOUT, bool BN>
__global__ void __launch_bounds__(256) k_gemm(const float* __restrict__ A,
                                              const float* __restrict__ W, int n) {
    const float* __restrict__ Ap = BN ? (const float*)g_h : A;
    constexpr int TN = NOUT / 16;     // 8 (NOUT=128) or 4 (NOUT=64)
    __shared__ float As[8][132];
    __shared__ float Ws[8][NOUT];
    __shared__ float sc[128], sf[128];
    int tid = threadIdx.x;
    int tx = tid & 15, ty = tid >> 4;
    int r0 = blockIdx.x * 128;

    if (BN) {
        if (tid < 128) { sc[tid] = g_scale[tid]; sf[tid] = g_shift[tid]; }
        __syncthreads();
    }

    float acc[8][TN];
#pragma unroll
    for (int i = 0; i < 8; i++)
#pragma unroll
        for (int t = 0; t < TN; t++) acc[i][t] = 0.f;

    int ar = tid >> 1;            // 0..127 row in tile
    int kh = (tid & 1) * 4;       // 0 or 4

    for (int k0 = 0; k0 < 128; k0 += 8) {
        float4 av = make_float4(0.f, 0.f, 0.f, 0.f);
        if (r0 + ar < n) av = *(const float4*)&Ap[(r0 + ar) * 128 + k0 + kh];
        if (BN) {
            int kb = k0 + kh;
            av.x = fmaxf(av.x * sc[kb + 0] + sf[kb + 0], 0.f);
            av.y = fmaxf(av.y * sc[kb + 1] + sf[kb + 1], 0.f);
            av.z = fmaxf(av.z * sc[kb + 2] + sf[kb + 2], 0.f);
            av.w = fmaxf(av.w * sc[kb + 3] + sf[kb + 3], 0.f);
        }
        As[kh + 0][ar] = av.x; As[kh + 1][ar] = av.y;
        As[kh + 2][ar] = av.z; As[kh + 3][ar] = av.w;

        for (int l = tid; l < 2 * NOUT; l += 256) {     // 8*NOUT/4 float4s
            int kk = l / (NOUT / 4);
            int cc = (l % (NOUT / 4)) * 4;
            *(float4*)&Ws[kk][cc] = *(const float4*)&W[(k0 + kk) * NOUT + cc];
        }
        __syncthreads();

#pragma unroll
        for (int kk = 0; kk < 8; kk++) {
            float a[8], b[TN];
            *(float4*)&a[0] = *(float4*)&As[kk][ty * 8 + 0];
            *(float4*)&a[4] = *(float4*)&As[kk][ty * 8 + 4];
#pragma unroll
            for (int t4 = 0; t4 < TN; t4 += 4)
                *(float4*)&b[t4] = *(float4*)&Ws[kk][tx * TN + t4];
#pragma unroll
            for (int i = 0; i < 8; i++)
#pragma unroll
                for (int t = 0; t < TN; t++)
                    acc[i][t] += a[i] * b[t];
        }
        __syncthreads();
    }

#pragma unroll
    for (int i = 0; i < 8; i++) {
        int r = r0 + ty * 8 + i;
        if (r < n) {
#pragma unroll
            for (int t4 = 0; t4 < TN; t4 += 4) {
                float4 o = make_float4(acc[i][t4], acc[i][t4 + 1], acc[i][t4 + 2], acc[i][t4 + 3]);
                *(float4*)&g_xp[r * NOUT + tx * TN + t4] = o;
            }
        }
    }
}

// ---------------- attention dot products ----------------
template <int C>
__global__ void k_edots(const float* __restrict__ asv, const float* __restrict__ adv, int n) {
    int w = (blockIdx.x * blockDim.x + threadIdx.x) >> 5;
    int lane = threadIdx.x & 31;
    if (w >= n) return;
    constexpr int V = C / 32;       // 4 or 2
    float s1 = 0.f, s2 = 0.f;
    if (V == 4) {
        float4 v = *(const float4*)&g_xp[w * C + lane * 4];
        float4 a = *(const float4*)&asv[lane * 4];
        float4 d = *(const float4*)&adv[lane * 4];
        s1 = v.x * a.x + v.y * a.y + v.z * a.z + v.w * a.w;
        s2 = v.x * d.x + v.y * d.y + v.z * d.z + v.w * d.w;
    } else {
        float2 v = *(const float2*)&g_xp[w * C + lane * 2];
        float2 a = *(const float2*)&asv[lane * 2];
        float2 d = *(const float2*)&adv[lane * 2];
        s1 = v.x * a.x + v.y * a.y;
        s2 = v.x * d.x + v.y * d.y;
    }
#pragma unroll
    for (int off = 16; off; off >>= 1) {
        s1 += __shfl_xor_sync(0xffffffffu, s1, off);
        s2 += __shfl_xor_sync(0xffffffffu, s2, off);
    }
    if (lane == 0) { g_es[w] = s1; g_ed[w] = s2; }
}

// ---------------- GAT aggregation: one WARP per destination node ----------------
// out == nullptr -> write g_h
template <int C>
__global__ void k_agg(const float* __restrict__ bias, float* __restrict__ out) {
    float* __restrict__ outp = out ? out : (float*)g_h;
    int node = (blockIdx.x * blockDim.x + threadIdx.x) >> 5;
    int lane = threadIdx.x & 31;
    if (node >= NN) return;
    int beg = g_rowptr[node], end = g_rowptr[node + 1];
    float edv = g_ed[node];

    // pass 1: segment max of leaky(al)
    float m = -3.4e38f;
    for (int p = beg + lane; p < end; p += 32) {
        float al = g_es[g_ssrc[p]] + edv;
        al = al > 0.f ? al : 0.2f * al;
        m = fmaxf(m, al);
    }
#pragma unroll
    for (int off = 16; off; off >>= 1) m = fmaxf(m, __shfl_xor_sync(0xffffffffu, m, off));

    // pass 2: chunk of 32 edges at a time; weights in regs, shfl-broadcast
    constexpr int V = C / 32;       // floats per lane
    float acc[V];
#pragma unroll
    for (int v = 0; v < V; v++) acc[v] = 0.f;
    float dp = 0.f;

    for (int base = beg; base < end; base += 32) {
        int p = base + lane;
        float w = 0.f; int s = 0;
        if (p < end) {
            s = g_ssrc[p];
            float al = g_es[s] + edv;
            al = al > 0.f ? al : 0.2f * al;
            w = __expf(al - m);
            dp += w;
        }
        int cnt = min(32, end - base);
        for (int j = 0; j < cnt; j++) {
            float wj = __shfl_sync(0xffffffffu, w, j);
            int   sj = __shfl_sync(0xffffffffu, s, j);
            if (V == 4) {
                float4 xv = *(const float4*)&g_xp[sj * C + lane * 4];
                acc[0] += wj * xv.x; acc[1] += wj * xv.y;
                acc[2] += wj * xv.z; acc[3] += wj * xv.w;
            } else {
                float2 xv = *(const float2*)&g_xp[sj * C + lane * 2];
                acc[0] += wj * xv.x; acc[1] += wj * xv.y;
            }
        }
    }
#pragma unroll
    for (int off = 16; off; off >>= 1) dp += __shfl_xor_sync(0xffffffffu, dp, off);
    float inv = 1.f / dp;

    if (V == 4) {
        float4 b4 = *(const float4*)&bias[lane * 4];
        float4 o = make_float4(acc[0] * inv + b4.x, acc[1] * inv + b4.y,
                               acc[2] * inv + b4.z, acc[3] * inv + b4.w);
        *(float4*)&outp[node * C + lane * 4] = o;
    } else {
        float2 b2 = *(const float2*)&bias[lane * 2];
        float2 o = make_float2(acc[0] * inv + b2.x, acc[1] * inv + b2.y);
        *(float2*)&outp[node * C + lane * 2] = o;
    }
}

// ---------------- BatchNorm stats ----------------
__global__ void k_zero_stats() {
    int i = threadIdx.x;
    if (i < 2 * DHx) g_stats[i] = 0.f;
}

__global__ void k_bnstats(int n) {
    int c = threadIdx.x;
    float s = 0.f, sq = 0.f;
    for (int r = blockIdx.x; r < n; r += gridDim.x) {
        float v = g_h[r * 128 + c];
        s += v; sq += v * v;
    }
    atomicAdd(&g_stats[c], s);
    atomicAdd(&g_stats[128 + c], sq);
}

__global__ void k_bnparams(const float* __restrict__ g, const float* __restrict__ be, int n) {
    int c = threadIdx.x;
    float inv_n = 1.f / (float)n;
    float m = g_stats[c] * inv_n;
    float v = g_stats[128 + c] * inv_n - m * m;
    float scv = g[c] * rsqrtf(v + 1e-5f);
    g_scale[c] = scv;
    g_shift[c] = be[c] - m * scv;
}

// ---------------- pooling: g_pool[128,64] = gp[128,n] @ hn[n,64] ----------------
__global__ void k_zero_pool() {
    int i = blockIdx.x * blockDim.x + threadIdx.x;
    if (i < NGx * DOUTx) g_pool[i] = 0.f;
}

__global__ void k_pool(const float* __restrict__ gp, const float* __restrict__ hn, int n) {
    __shared__ float gpt[32][129];
    __shared__ float hnt[32][65];
    int tid = threadIdx.x;
    int tn = (tid & 15) * 4;
    int tm = (tid >> 4) * 8;
    float acc[8][4];
#pragma unroll
    for (int a = 0; a < 8; a++)
#pragma unroll
        for (int b = 0; b < 4; b++) acc[a][b] = 0.f;

    int kpb  = (n + gridDim.x - 1) / gridDim.x;
    int kbeg = blockIdx.x * kpb;
    int kend = min(n, kbeg + kpb);

    for (int k0 = kbeg; k0 < kend; k0 += 32) {
        int kt = min(32, kend - k0);
        for (int l = tid; l < 128 * 32; l += 256) {
            int m = l >> 5, kk = l & 31;
            gpt[kk][m] = (kk < kt) ? gp[m * n + k0 + kk] : 0.f;
        }
        for (int l = tid; l < 32 * 64; l += 256) {
            int kk = l >> 6, cc = l & 63;
            hnt[kk][cc] = (kk < kt) ? hn[(k0 + kk) * 64 + cc] : 0.f;
        }
        __syncthreads();
#pragma unroll 4
        for (int kk = 0; kk < 32; kk++) {
            float h0 = hnt[kk][tn + 0], h1 = hnt[kk][tn + 1];
            float h2 = hnt[kk][tn + 2], h3 = hnt[kk][tn + 3];
#pragma unroll
            for (int a = 0; a < 8; a++) {
                float g = gpt[kk][tm + a];
                acc[a][0] += g * h0;
                acc[a][1] += g * h1;
                acc[a][2] += g * h2;
                acc[a][3] += g * h3;
            }
        }
        __syncthreads();
    }
#pragma unroll
    for (int a = 0; a < 8; a++)
#pragma unroll
        for (int b = 0; b < 4; b++)
            atomicAdd(&g_pool[(tm + a) * 64 + tn + b], acc[a][b]);
}

__global__ void k_copy_pool(float* __restrict__ out) {
    int i = blockIdx.x * blockDim.x + threadIdx.x;
    if (i < NGx * DOUTx) out[i] = g_pool[i];
}

// ---------------- launch ----------------
extern "C" void kernel_launch(void* const* d_in, const int* in_sizes, int n_in,
                              void* d_out, int out_size) {
    const float* x   = (const float*)d_in[0];
    const void*  ei  = (const void*)d_in[1];
    const float* gp  = (const float*)d_in[2];
    const float* W1  = (const float*)d_in[3];
    const float* as1 = (const float*)d_in[4];
    const float* ad1 = (const float*)d_in[5];
    const float* b1  = (const float*)d_in[6];
    const float* g1  = (const float*)d_in[7];
    const float* be1 = (const float*)d_in[8];
    const float* W2  = (const float*)d_in[9];
    const float* as2 = (const float*)d_in[10];
    const float* ad2 = (const float*)d_in[11];
    const float* b2  = (const float*)d_in[12];
    const float* g2  = (const float*)d_in[13];
    const float* be2 = (const float*)d_in[14];
    const float* W3  = (const float*)d_in[15];
    const float* as3 = (const float*)d_in[16];
    const float* ad3 = (const float*)d_in[17];
    const float* b3  = (const float*)d_in[18];

    float* out       = (float*)d_out;
    float* out_pool  = out;                    // [128,64]
    float* out_nodes = out + NGx * DOUTx;      // [50000,64]

    const int T = 256;

    k_detect<<<1, 256>>>((const unsigned int*)ei);

    // CSR by destination (shared by all 3 layers)
    k_zero_cnt<<<(NN + T - 1) / T, T>>>();
    k_hist<<<(ETOT + T - 1) / T, T>>>(ei);
    k_scan1<<<49, 1024>>>();
    k_scan2<<<1, 64>>>();
    k_scan3<<<49, 1024>>>();
    k_scatter<<<(ETOT + T - 1) / T, T>>>(ei);

    int gemm_blocks = (NN + 127) / 128;
    int warp_blocks = (NN * 32 + T - 1) / T;

    // ---- Layer 1 ----
    k_gemm<128, false><<<gemm_blocks, 256>>>(x, W1, NN);
    k_edots<128><<<warp_blocks, T>>>(as1, ad1, NN);
    k_agg<128><<<warp_blocks, T>>>(b1, nullptr);
    k_zero_stats<<<1, 256>>>();
    k_bnstats<<<512, 128>>>(NN);
    k_bnparams<<<1, 128>>>(g1, be1, NN);

    // ---- Layer 2 (BN+ReLU folded into GEMM A-load) ----
    k_gemm<128, true><<<gemm_blocks, 256>>>(nullptr, W2, NN);
    k_edots<128><<<warp_blocks, T>>>(as2, ad2, NN);
    k_agg<128><<<warp_blocks, T>>>(b2, nullptr);
    k_zero_stats<<<1, 256>>>();
    k_bnstats<<<512, 128>>>(NN);
    k_bnparams<<<1, 128>>>(g2, be2, NN);

    // ---- Layer 3 (64 out channels, BN folded, no BN after) ----
    k_gemm<64, true><<<gemm_blocks, 256>>>(nullptr, W3, NN);
    k_edots<64><<<warp_blocks, T>>>(as3, ad3, NN);
    k_agg<64><<<warp_blocks, T>>>(b3, out_nodes);

    // ---- pooling ----
    k_zero_pool<<<(NGx * DOUTx + T - 1) / T, T>>>();
    k_pool<<<128, 256>>>(gp, out_nodes, NN);
    k_copy_pool<<<(NGx * DOUTx + T - 1) / T, T>>>(out_pool);
}

// round 5
// speedup vs baseline: 1.6468x; 1.1179x over previous
#include <cuda_runtime.h>
#include <cuda_bf16.h>
#include <cstdint>

#define NN   50000
#define EE   800000
#define ETOT (EE + NN)     // edges + self loops = 850000
#define DHx  128
#define DOUTx 64
#define NGx  128

// ---------------- device scratch ----------------
__device__ int   g_is64;
__device__ int   g_cnt[NN];
__device__ int   g_btot[64];
__device__ int   g_boff[64];
__device__ int   g_rowptr[NN + 1];
__device__ int   g_cur[NN];
__device__ int   g_ssrc[ETOT];
__device__ float g_xp[NN * DHx];
__device__ float g_h [NN * DHx];
__device__ float g_es[NN];
__device__ float g_ed[NN];
__device__ float g_stats[2 * DHx];
__device__ float g_scale[DHx];
__device__ float g_shift[DHx];
__device__ float g_pool[NGx * DOUTx];

// ---------------- edge dtype detection ----------------
__global__ void k_detect(const unsigned int* __restrict__ ei_raw) {
    __shared__ unsigned int sh[256];
    int t = threadIdx.x;
    unsigned int v = 0;
    for (int i = t; i < 1024; i += 256) v |= ei_raw[2 * i + 1];
    sh[t] = v;
    __syncthreads();
    for (int off = 128; off; off >>= 1) {
        if (t < off) sh[t] |= sh[t + off];
        __syncthreads();
    }
    if (t == 0) g_is64 = (sh[0] == 0) ? 1 : 0;
}

__device__ __forceinline__ int edge_at(const void* ei, int idx) {
    int v;
    if (g_is64) v = (int)((const long long*)ei)[idx];
    else        v = ((const int*)ei)[idx];
    v = v < 0 ? 0 : (v >= NN ? NN - 1 : v);
    return v;
}

// ---------------- CSR build ----------------
__global__ void k_zero_cnt() {
    int i = blockIdx.x * blockDim.x + threadIdx.x;
    if (i < NN) g_cnt[i] = 0;
}

__global__ void k_hist(const void* __restrict__ ei) {
    int e = blockIdx.x * blockDim.x + threadIdx.x;
    if (e >= ETOT) return;
    int dst = (e < EE) ? edge_at(ei, EE + e) : (e - EE);
    atomicAdd(&g_cnt[dst], 1);
}

__global__ void k_scan1() {
    int t = threadIdx.x;
    int i = blockIdx.x * 1024 + t;
    int v = (i < NN) ? g_cnt[i] : 0;
    __shared__ int sh[1024];
    sh[t] = v;
    __syncthreads();
    for (int off = 1; off < 1024; off <<= 1) {
        int a = (t >= off) ? sh[t - off] : 0;
        __syncthreads();
        sh[t] += a;
        __syncthreads();
    }
    if (i < NN) g_cnt[i] = sh[t] - v;
    if (t == 1023) g_btot[blockIdx.x] = sh[1023];
}

__global__ void k_scan2() {
    int t = threadIdx.x;
    int v = (t < 49) ? g_btot[t] : 0;
    __shared__ int sh[64];
    sh[t] = v;
    __syncthreads();
    for (int off = 1; off < 64; off <<= 1) {
        int a = (t >= off) ? sh[t - off] : 0;
        __syncthreads();
        sh[t] += a;
        __syncthreads();
    }
    if (t < 49) g_boff[t] = sh[t] - v;
}

__global__ void k_scan3() {
    int i = blockIdx.x * 1024 + threadIdx.x;
    if (i < NN) {
        int rp = g_cnt[i] + g_boff[blockIdx.x];
        g_rowptr[i] = rp;
        g_cur[i] = rp;
    }
    if (i == 0) g_rowptr[NN] = ETOT;
}

__global__ void k_scatter(const void* __restrict__ ei) {
    int e = blockIdx.x * blockDim.x + threadIdx.x;
    if (e >= ETOT) return;
    int s, d;
    if (e < EE) { s = edge_at(ei, e); d = edge_at(ei, EE + e); }
    else        { s = e - EE;         d = s; }
    int pos = atomicAdd(&g_cur[d], 1);
    g_ssrc[pos] = s;
}

// ---------------- GEMM + fused attention dots ----------------
// g_xp[n,NOUT] = act(A)[n,128] @ W[128,NOUT];  g_es/g_ed = xp @ as / xp @ ad
// BN=true: A = relu(g_h * g_scale + g_shift) computed on load
template <int NOUT, bool BN>
__global__ void __launch_bounds__(256) k_gemm(const float* __restrict__ A,
                                              const float* __restrict__ W,
                                              const float* __restrict__ asv,
                                              const float* __restrict__ adv, int n) {
    const float* __restrict__ Ap = BN ? (const float*)g_h : A;
    constexpr int TN = NOUT / 16;     // 8 (NOUT=128) or 4 (NOUT=64)
    __shared__ float As[8][132];
    __shared__ float Ws[8][NOUT];
    __shared__ float sc[128], sf[128];
    int tid = threadIdx.x;
    int tx = tid & 15, ty = tid >> 4;
    int r0 = blockIdx.x * 128;

    if (BN) {
        if (tid < 128) { sc[tid] = g_scale[tid]; sf[tid] = g_shift[tid]; }
        __syncthreads();
    }

    float acc[8][TN];
#pragma unroll
    for (int i = 0; i < 8; i++)
#pragma unroll
        for (int t = 0; t < TN; t++) acc[i][t] = 0.f;

    int ar = tid >> 1;            // 0..127 row in tile
    int kh = (tid & 1) * 4;       // 0 or 4

    for (int k0 = 0; k0 < 128; k0 += 8) {
        float4 av = make_float4(0.f, 0.f, 0.f, 0.f);
        if (r0 + ar < n) av = *(const float4*)&Ap[(r0 + ar) * 128 + k0 + kh];
        if (BN) {
            int kb = k0 + kh;
            av.x = fmaxf(av.x * sc[kb + 0] + sf[kb + 0], 0.f);
            av.y = fmaxf(av.y * sc[kb + 1] + sf[kb + 1], 0.f);
            av.z = fmaxf(av.z * sc[kb + 2] + sf[kb + 2], 0.f);
            av.w = fmaxf(av.w * sc[kb + 3] + sf[kb + 3], 0.f);
        }
        As[kh + 0][ar] = av.x; As[kh + 1][ar] = av.y;
        As[kh + 2][ar] = av.z; As[kh + 3][ar] = av.w;

        for (int l = tid; l < 2 * NOUT; l += 256) {
            int kk = l / (NOUT / 4);
            int cc = (l % (NOUT / 4)) * 4;
            *(float4*)&Ws[kk][cc] = *(const float4*)&W[(k0 + kk) * NOUT + cc];
        }
        __syncthreads();

#pragma unroll
        for (int kk = 0; kk < 8; kk++) {
            float a[8], b[TN];
            *(float4*)&a[0] = *(float4*)&As[kk][ty * 8 + 0];
            *(float4*)&a[4] = *(float4*)&As[kk][ty * 8 + 4];
#pragma unroll
            for (int t4 = 0; t4 < TN; t4 += 4)
                *(float4*)&b[t4] = *(float4*)&Ws[kk][tx * TN + t4];
#pragma unroll
            for (int i = 0; i < 8; i++)
#pragma unroll
                for (int t = 0; t < TN; t++)
                    acc[i][t] += a[i] * b[t];
        }
        __syncthreads();
    }

    // attention vectors for this thread's column strip
    float avs[TN], avd[TN];
#pragma unroll
    for (int t4 = 0; t4 < TN; t4 += 4) {
        *(float4*)&avs[t4] = *(const float4*)&asv[tx * TN + t4];
        *(float4*)&avd[t4] = *(const float4*)&adv[tx * TN + t4];
    }

#pragma unroll
    for (int i = 0; i < 8; i++) {
        int r = r0 + ty * 8 + i;
        if (r < n) {
#pragma unroll
            for (int t4 = 0; t4 < TN; t4 += 4) {
                float4 o = make_float4(acc[i][t4], acc[i][t4 + 1], acc[i][t4 + 2], acc[i][t4 + 3]);
                *(float4*)&g_xp[r * NOUT + tx * TN + t4] = o;
            }
        }
        // fused e_src/e_dst: partial dot over this thread's strip, reduce over tx (width 16)
        float ps = 0.f, pd = 0.f;
#pragma unroll
        for (int t = 0; t < TN; t++) { ps += acc[i][t] * avs[t]; pd += acc[i][t] * avd[t]; }
#pragma unroll
        for (int off = 8; off; off >>= 1) {
            ps += __shfl_xor_sync(0xffffffffu, ps, off, 16);
            pd += __shfl_xor_sync(0xffffffffu, pd, off, 16);
        }
        if (tx == 0 && r < n) { g_es[r] = ps; g_ed[r] = pd; }
    }
}

// ---------------- GAT aggregation: one WARP per destination node ----------------
template <int C>
__global__ void k_agg(const float* __restrict__ bias, float* __restrict__ out) {
    float* __restrict__ outp = out ? out : (float*)g_h;
    int node = (blockIdx.x * blockDim.x + threadIdx.x) >> 5;
    int lane = threadIdx.x & 31;
    if (node >= NN) return;
    int beg = g_rowptr[node], end = g_rowptr[node + 1];
    int deg = end - beg;
    float edv = g_ed[node];

    constexpr int V = C / 32;
    float acc[V];
#pragma unroll
    for (int v = 0; v < V; v++) acc[v] = 0.f;
    float dp;

    if (deg <= 32) {
        // single pass: logits live in registers
        int p = beg + lane;
        int s = 0;
        float al = -3.4e38f;
        if (p < end) {
            s = g_ssrc[p];
            float t = g_es[s] + edv;
            al = t > 0.f ? t : 0.2f * t;
        }
        float m = al;
#pragma unroll
        for (int off = 16; off; off >>= 1) m = fmaxf(m, __shfl_xor_sync(0xffffffffu, m, off));
        float w = (p < end) ? __expf(al - m) : 0.f;
        dp = w;
#pragma unroll
        for (int off = 16; off; off >>= 1) dp += __shfl_xor_sync(0xffffffffu, dp, off);

#pragma unroll 4
        for (int j = 0; j < deg; j++) {
            float wj = __shfl_sync(0xffffffffu, w, j);
            int   sj = __shfl_sync(0xffffffffu, s, j);
            if (V == 4) {
                float4 xv = *(const float4*)&g_xp[sj * C + lane * 4];
                acc[0] += wj * xv.x; acc[1] += wj * xv.y;
                acc[2] += wj * xv.z; acc[3] += wj * xv.w;
            } else {
                float2 xv = *(const float2*)&g_xp[sj * C + lane * 2];
                acc[0] += wj * xv.x; acc[1] += wj * xv.y;
            }
        }
    } else {
        // rare long-row fallback: two-pass
        float m = -3.4e38f;
        for (int p = beg + lane; p < end; p += 32) {
            float al = g_es[g_ssrc[p]] + edv;
            al = al > 0.f ? al : 0.2f * al;
            m = fmaxf(m, al);
        }
#pragma unroll
        for (int off = 16; off; off >>= 1) m = fmaxf(m, __shfl_xor_sync(0xffffffffu, m, off));

        dp = 0.f;
        for (int base = beg; base < end; base += 32) {
            int p = base + lane;
            float w = 0.f; int s = 0;
            if (p < end) {
                s = g_ssrc[p];
                float al = g_es[s] + edv;
                al = al > 0.f ? al : 0.2f * al;
                w = __expf(al - m);
                dp += w;
            }
            int cnt = min(32, end - base);
#pragma unroll 4
            for (int j = 0; j < cnt; j++) {
                float wj = __shfl_sync(0xffffffffu, w, j);
                int   sj = __shfl_sync(0xffffffffu, s, j);
                if (V == 4) {
                    float4 xv = *(const float4*)&g_xp[sj * C + lane * 4];
                    acc[0] += wj * xv.x; acc[1] += wj * xv.y;
                    acc[2] += wj * xv.z; acc[3] += wj * xv.w;
                } else {
                    float2 xv = *(const float2*)&g_xp[sj * C + lane * 2];
                    acc[0] += wj * xv.x; acc[1] += wj * xv.y;
                }
            }
        }
#pragma unroll
        for (int off = 16; off; off >>= 1) dp += __shfl_xor_sync(0xffffffffu, dp, off);
    }

    float inv = 1.f / dp;
    if (V == 4) {
        float4 b4 = *(const float4*)&bias[lane * 4];
        float4 o = make_float4(acc[0] * inv + b4.x, acc[1] * inv + b4.y,
                               acc[2] * inv + b4.z, acc[3] * inv + b4.w);
        *(float4*)&outp[node * C + lane * 4] = o;
    } else {
        float2 b2 = *(const float2*)&bias[lane * 2];
        float2 o = make_float2(acc[0] * inv + b2.x, acc[1] * inv + b2.y);
        *(float2*)&outp[node * C + lane * 2] = o;
    }
}

// ---------------- BatchNorm stats ----------------
__global__ void k_zero_stats() {
    int i = threadIdx.x;
    if (i < 2 * DHx) g_stats[i] = 0.f;
}

__global__ void k_bnstats(int n) {
    int c = threadIdx.x;
    float s = 0.f, sq = 0.f;
    for (int r = blockIdx.x; r < n; r += gridDim.x) {
        float v = g_h[r * 128 + c];
        s += v; sq += v * v;
    }
    atomicAdd(&g_stats[c], s);
    atomicAdd(&g_stats[128 + c], sq);
}

__global__ void k_bnparams(const float* __restrict__ g, const float* __restrict__ be, int n) {
    int c = threadIdx.x;
    float inv_n = 1.f / (float)n;
    float m = g_stats[c] * inv_n;
    float v = g_stats[128 + c] * inv_n - m * m;
    float scv = g[c] * rsqrtf(v + 1e-5f);
    g_scale[c] = scv;
    g_shift[c] = be[c] - m * scv;
}

// ---------------- pooling ----------------
__global__ void k_zero_pool() {
    int i = blockIdx.x * blockDim.x + threadIdx.x;
    if (i < NGx * DOUTx) g_pool[i] = 0.f;
}

__global__ void k_pool(const float* __restrict__ gp, const float* __restrict__ hn, int n) {
    __shared__ float gpt[32][129];
    __shared__ float hnt[32][65];
    int tid = threadIdx.x;
    int tn = (tid & 15) * 4;
    int tm = (tid >> 4) * 8;
    float acc[8][4];
#pragma unroll
    for (int a = 0; a < 8; a++)
#pragma unroll
        for (int b = 0; b < 4; b++) acc[a][b] = 0.f;

    int kpb  = (n + gridDim.x - 1) / gridDim.x;
    int kbeg = blockIdx.x * kpb;
    int kend = min(n, kbeg + kpb);

    for (int k0 = kbeg; k0 < kend; k0 += 32) {
        int kt = min(32, kend - k0);
        for (int l = tid; l < 128 * 32; l += 256) {
            int m = l >> 5, kk = l & 31;
            gpt[kk][m] = (kk < kt) ? gp[m * n + k0 + kk] : 0.f;
        }
        for (int l = tid; l < 32 * 64; l += 256) {
            int kk = l >> 6, cc = l & 63;
            hnt[kk][cc] = (kk < kt) ? hn[(k0 + kk) * 64 + cc] : 0.f;
        }
        __syncthreads();
#pragma unroll 4
        for (int kk = 0; kk < 32; kk++) {
            float h0 = hnt[kk][tn + 0], h1 = hnt[kk][tn + 1];
            float h2 = hnt[kk][tn + 2], h3 = hnt[kk][tn + 3];
#pragma unroll
            for (int a = 0; a < 8; a++) {
                float g = gpt[kk][tm + a];
                acc[a][0] += g * h0;
                acc[a][1] += g * h1;
                acc[a][2] += g * h2;
                acc[a][3] += g * h3;
            }
        }
        __syncthreads();
    }
#pragma unroll
    for (int a = 0; a < 8; a++)
#pragma unroll
        for (int b = 0; b < 4; b++)
            atomicAdd(&g_pool[(tm + a) * 64 + tn + b], acc[a][b]);
}

__global__ void k_copy_pool(float* __restrict__ out) {
    int i = blockIdx.x * blockDim.x + threadIdx.x;
    if (i < NGx * DOUTx) out[i] = g_pool[i];
}

// ---------------- launch ----------------
extern "C" void kernel_launch(void* const* d_in, const int* in_sizes, int n_in,
                              void* d_out, int out_size) {
    const float* x   = (const float*)d_in[0];
    const void*  ei  = (const void*)d_in[1];
    const float* gp  = (const float*)d_in[2];
    const float* W1  = (const float*)d_in[3];
    const float* as1 = (const float*)d_in[4];
    const float* ad1 = (const float*)d_in[5];
    const float* b1  = (const float*)d_in[6];
    const float* g1  = (const float*)d_in[7];
    const float* be1 = (const float*)d_in[8];
    const float* W2  = (const float*)d_in[9];
    const float* as2 = (const float*)d_in[10];
    const float* ad2 = (const float*)d_in[11];
    const float* b2  = (const float*)d_in[12];
    const float* g2  = (const float*)d_in[13];
    const float* be2 = (const float*)d_in[14];
    const float* W3  = (const float*)d_in[15];
    const float* as3 = (const float*)d_in[16];
    const float* ad3 = (const float*)d_in[17];
    const float* b3  = (const float*)d_in[18];

    float* out       = (float*)d_out;
    float* out_pool  = out;                    // [128,64]
    float* out_nodes = out + NGx * DOUTx;      // [50000,64]

    const int T = 256;
    int gemm_blocks = (NN + 127) / 128;
    int warp_blocks = (NN * 32 + T - 1) / T;

    // launches 0-2, then GEMM-1 as launch #3 (= ncu's profiled slot)
    k_detect<<<1, 256>>>((const unsigned int*)ei);
    k_zero_cnt<<<(NN + T - 1) / T, T>>>();
    k_hist<<<(ETOT + T - 1) / T, T>>>(ei);
    k_gemm<128, false><<<gemm_blocks, 256>>>(x, W1, as1, ad1, NN);   // <- profiled

    // rest of CSR build (independent of gemm)
    k_scan1<<<49, 1024>>>();
    k_scan2<<<1, 64>>>();
    k_scan3<<<49, 1024>>>();
    k_scatter<<<(ETOT + T - 1) / T, T>>>(ei);

    // ---- Layer 1 aggregation + BN stats ----
    k_agg<128><<<warp_blocks, T>>>(b1, nullptr);
    k_zero_stats<<<1, 256>>>();
    k_bnstats<<<512, 128>>>(NN);
    k_bnparams<<<1, 128>>>(g1, be1, NN);

    // ---- Layer 2 (BN+ReLU folded into GEMM A-load) ----
    k_gemm<128, true><<<gemm_blocks, 256>>>(nullptr, W2, as2, ad2, NN);
    k_agg<128><<<warp_blocks, T>>>(b2, nullptr);
    k_zero_stats<<<1, 256>>>();
    k_bnstats<<<512, 128>>>(NN);
    k_bnparams<<<1, 128>>>(g2, be2, NN);

    // ---- Layer 3 ----
    k_gemm<64, true><<<gemm_blocks, 256>>>(nullptr, W3, as3, ad3, NN);
    k_agg<64><<<warp_blocks, T>>>(b3, out_nodes);

    // ---- pooling ----
    k_zero_pool<<<(NGx * DOUTx + T - 1) / T, T>>>();
    k_pool<<<128, 256>>>(gp, out_nodes, NN);
    k_copy_pool<<<(NGx * DOUTx + T - 1) / T, T>>>(out_pool);
}

// round 7
// speedup vs baseline: 1.7116x; 1.0393x over previous
#include <cuda_runtime.h>
#include <cuda_bf16.h>
#include <cstdint>

#define NN   50000
#define EE   800000
#define ETOT (EE + NN)
#define DHx  128
#define DOUTx 64
#define NGx  128

// ---------------- device scratch ----------------
__device__ int   g_is64;
__device__ int   g_cnt[NN];
__device__ int   g_btot[64];
__device__ int   g_boff[64];
__device__ int   g_rowptr[NN + 1];
__device__ int   g_cur[NN];
__device__ int   g_ssrc[ETOT];
__device__ float g_xp[NN * DHx];
__device__ float g_h [NN * DHx];
__device__ float g_es[NN];
__device__ float g_ed[NN];
__device__ float g_stats[2 * DHx];
__device__ float g_scale[DHx];
__device__ float g_shift[DHx];
__device__ float g_pool[NGx * DOUTx];
__device__ __nv_bfloat16 g_bhi[128 * 128];   // W^T hi split [n][k]
__device__ __nv_bfloat16 g_blo[128 * 128];   // W^T lo split

__device__ __forceinline__ uint32_t pack_bf2(float a, float b) {
    __nv_bfloat162 t = __floats2bfloat162_rn(a, b);
    return *(uint32_t*)&t;
}

__device__ __forceinline__ void mma_bf16(float* c, uint32_t a0, uint32_t a1, uint32_t a2,
                                         uint32_t a3, uint32_t b0, uint32_t b1) {
    asm volatile(
        "mma.sync.aligned.m16n8k16.row.col.f32.bf16.bf16.f32 "
        "{%0,%1,%2,%3},{%4,%5,%6,%7},{%8,%9},{%0,%1,%2,%3};"
        : "+f"(c[0]), "+f"(c[1]), "+f"(c[2]), "+f"(c[3])
        : "r"(a0), "r"(a1), "r"(a2), "r"(a3), "r"(b0), "r"(b1));
}

// ---------------- edge dtype detection ----------------
__global__ void k_detect(const unsigned int* __restrict__ ei_raw) {
    __shared__ unsigned int sh[256];
    int t = threadIdx.x;
    unsigned int v = 0;
    for (int i = t; i < 1024; i += 256) v |= ei_raw[2 * i + 1];
    sh[t] = v;
    __syncthreads();
    for (int off = 128; off; off >>= 1) {
        if (t < off) sh[t] |= sh[t + off];
        __syncthreads();
    }
    if (t == 0) g_is64 = (sh[0] == 0) ? 1 : 0;
}

__device__ __forceinline__ int edge_at(const void* ei, int idx) {
    int v;
    if (g_is64) v = (int)((const long long*)ei)[idx];
    else        v = ((const int*)ei)[idx];
    v = v < 0 ? 0 : (v >= NN ? NN - 1 : v);
    return v;
}

// ---------------- CSR build ----------------
__global__ void k_zero_cnt() {
    int i = blockIdx.x * blockDim.x + threadIdx.x;
    if (i < NN) g_cnt[i] = 0;
}
__global__ void k_hist(const void* __restrict__ ei) {
    int e = blockIdx.x * blockDim.x + threadIdx.x;
    if (e >= ETOT) return;
    int dst = (e < EE) ? edge_at(ei, EE + e) : (e - EE);
    atomicAdd(&g_cnt[dst], 1);
}
__global__ void k_scan1() {
    int t = threadIdx.x;
    int i = blockIdx.x * 1024 + t;
    int v = (i < NN) ? g_cnt[i] : 0;
    __shared__ int sh[1024];
    sh[t] = v;
    __syncthreads();
    for (int off = 1; off < 1024; off <<= 1) {
        int a = (t >= off) ? sh[t - off] : 0;
        __syncthreads();
        sh[t] += a;
        __syncthreads();
    }
    if (i < NN) g_cnt[i] = sh[t] - v;
    if (t == 1023) g_btot[blockIdx.x] = sh[1023];
}
__global__ void k_scan2() {
    int t = threadIdx.x;
    int v = (t < 49) ? g_btot[t] : 0;
    __shared__ int sh[64];
    sh[t] = v;
    __syncthreads();
    for (int off = 1; off < 64; off <<= 1) {
        int a = (t >= off) ? sh[t - off] : 0;
        __syncthreads();
        sh[t] += a;
        __syncthreads();
    }
    if (t < 49) g_boff[t] = sh[t] - v;
}
__global__ void k_scan3() {
    int i = blockIdx.x * 1024 + threadIdx.x;
    if (i < NN) {
        int rp = g_cnt[i] + g_boff[blockIdx.x];
        g_rowptr[i] = rp;
        g_cur[i] = rp;
    }
    if (i == 0) g_rowptr[NN] = ETOT;
}
__global__ void k_scatter(const void* __restrict__ ei) {
    int e = blockIdx.x * blockDim.x + threadIdx.x;
    if (e >= ETOT) return;
    int s, d;
    if (e < EE) { s = edge_at(ei, e); d = edge_at(ei, EE + e); }
    else        { s = e - EE;         d = s; }
    int pos = atomicAdd(&g_cur[d], 1);
    g_ssrc[pos] = s;
}

// ---------------- W prep: transpose + bf16 hi/lo split ----------------
template <int NOUT>
__global__ void k_prepw(const float* __restrict__ W) {
    int i = blockIdx.x * blockDim.x + threadIdx.x;
    if (i >= NOUT * 128) return;
    int nrow = i >> 7, k = i & 127;            // B[n][k] = W[k][n]
    float w = W[k * NOUT + nrow];
    __nv_bfloat16 h = __float2bfloat16_rn(w);
    g_bhi[i] = h;
    g_blo[i] = __float2bfloat16_rn(w - __bfloat162float(h));
}

// ---------------- warp-MMA GEMM: 128 x NOUT tile, K=128, 3-term bf16 split --------
// dynamic smem layout (bytes):
//   0: sas(512) 512: sad(512) 1024: sc(512) 1536: sf(512)
//   2048: esp(2048) 4096: edp(2048) 6144: A_hi, A_lo, B_hi, B_lo (PAD=136 rows)
template <int NOUT, bool BN>
__global__ void __launch_bounds__(256) k_gemm_mma(const float* __restrict__ A,
                                                  const float* __restrict__ asv,
                                                  const float* __restrict__ adv, int n) {
    extern __shared__ char smem[];
    const float* __restrict__ Ap = BN ? (const float*)g_h : A;
    constexpr int PAD = 136;
    constexpr int ASZ = 128 * PAD;             // bf16 elems
    constexpr int BSZ = NOUT * PAD;
    float* sas = (float*)(smem);
    float* sad = (float*)(smem + 512);
    float* sc  = (float*)(smem + 1024);
    float* sf  = (float*)(smem + 1536);
    float* esp = (float*)(smem + 2048);
    float* edp = (float*)(smem + 4096);
    __nv_bfloat16* ah = (__nv_bfloat16*)(smem + 6144);
    __nv_bfloat16* al = ah + ASZ;
    __nv_bfloat16* bh = al + ASZ;
    __nv_bfloat16* bl = bh + BSZ;

    int tid = threadIdx.x, wid = tid >> 5, lane = tid & 31;
    int r0 = blockIdx.x * 128;

    if (tid < NOUT) { sas[tid] = asv[tid]; sad[tid] = adv[tid]; }
    if (BN && tid < 128) { sc[tid] = g_scale[tid]; sf[tid] = g_shift[tid]; }
    if (BN) __syncthreads();

    // A tile fp32 -> bf16 hi/lo (fused BN+ReLU)
    for (int l = tid; l < 128 * 32; l += 256) {
        int row = l >> 5, k = (l & 31) << 2;
        float4 v = make_float4(0.f, 0.f, 0.f, 0.f);
        if (r0 + row < n) v = *(const float4*)&Ap[(r0 + row) * 128 + k];
        if (BN) {
            v.x = fmaxf(v.x * sc[k + 0] + sf[k + 0], 0.f);
            v.y = fmaxf(v.y * sc[k + 1] + sf[k + 1], 0.f);
            v.z = fmaxf(v.z * sc[k + 2] + sf[k + 2], 0.f);
            v.w = fmaxf(v.w * sc[k + 3] + sf[k + 3], 0.f);
        }
        float h0 = __bfloat162float(__float2bfloat16_rn(v.x));
        float h1 = __bfloat162float(__float2bfloat16_rn(v.y));
        float h2 = __bfloat162float(__float2bfloat16_rn(v.z));
        float h3 = __bfloat162float(__float2bfloat16_rn(v.w));
        *(uint2*)&ah[row * PAD + k] = make_uint2(pack_bf2(v.x, v.y), pack_bf2(v.z, v.w));
        *(uint2*)&al[row * PAD + k] = make_uint2(pack_bf2(v.x - h0, v.y - h1),
                                                 pack_bf2(v.z - h2, v.w - h3));
    }
    // B hi/lo copy into padded smem
    for (int l = tid; l < NOUT * 32; l += 256) {
        int row = l >> 5, k = (l & 31) << 2;
        *(uint2*)&bh[row * PAD + k] = *(const uint2*)&g_bhi[row * 128 + k];
        *(uint2*)&bl[row * PAD + k] = *(const uint2*)&g_blo[row * 128 + k];
    }
    __syncthreads();

    constexpr int WN = (NOUT == 128) ? 32 : 16;      // warp n-width
    constexpr int NA = WN / 8;                       // n atoms per warp
    int wm = (wid & 1) * 64;
    int wn = (wid >> 1) * WN;
    int gq = lane >> 2, t2 = (lane & 3) * 2;

    float acc[4][NA][4];
#pragma unroll
    for (int i = 0; i < 4; i++)
#pragma unroll
        for (int j = 0; j < NA; j++)
#pragma unroll
            for (int q = 0; q < 4; q++) acc[i][j][q] = 0.f;

#pragma unroll
    for (int ks = 0; ks < 8; ks++) {
        int k0 = ks * 16;
        uint32_t fbh[NA][2], fbl[NA][2];
#pragma unroll
        for (int j = 0; j < NA; j++) {
            const __nv_bfloat16* pb = &bh[(wn + j * 8 + gq) * PAD + k0 + t2];
            fbh[j][0] = *(const uint32_t*)pb;
            fbh[j][1] = *(const uint32_t*)(pb + 8);
            const __nv_bfloat16* pl = &bl[(wn + j * 8 + gq) * PAD + k0 + t2];
            fbl[j][0] = *(const uint32_t*)pl;
            fbl[j][1] = *(const uint32_t*)(pl + 8);
        }
#pragma unroll
        for (int i = 0; i < 4; i++) {
            const __nv_bfloat16* pa = &ah[(wm + i * 16 + gq) * PAD + k0 + t2];
            uint32_t ah0 = *(const uint32_t*)pa;
            uint32_t ah1 = *(const uint32_t*)(pa + 8 * PAD);
            uint32_t ah2 = *(const uint32_t*)(pa + 8);
            uint32_t ah3 = *(const uint32_t*)(pa + 8 * PAD + 8);
            const __nv_bfloat16* qa = &al[(wm + i * 16 + gq) * PAD + k0 + t2];
            uint32_t al0 = *(const uint32_t*)qa;
            uint32_t al1 = *(const uint32_t*)(qa + 8 * PAD);
            uint32_t al2 = *(const uint32_t*)(qa + 8);
            uint32_t al3 = *(const uint32_t*)(qa + 8 * PAD + 8);
#pragma unroll
            for (int j = 0; j < NA; j++) {
                mma_bf16(acc[i][j], ah0, ah1, ah2, ah3, fbh[j][0], fbh[j][1]);
                mma_bf16(acc[i][j], ah0, ah1, ah2, ah3, fbl[j][0], fbl[j][1]);
                mma_bf16(acc[i][j], al0, al1, al2, al3, fbh[j][0], fbh[j][1]);
            }
        }
    }

    // epilogue: store xp + fused attention dot partials
    int wng = wid >> 1;                          // 0..3 column group
#pragma unroll
    for (int i = 0; i < 4; i++) {
        int rl = r0 + wm + i * 16 + gq;
        int rh = rl + 8;
        float psl = 0.f, pdl = 0.f, psh = 0.f, pdh = 0.f;
#pragma unroll
        for (int j = 0; j < NA; j++) {
            int c0 = wn + j * 8 + t2;
            if (rl < n) *(float2*)&g_xp[rl * NOUT + c0] = make_float2(acc[i][j][0], acc[i][j][1]);
            if (rh < n) *(float2*)&g_xp[rh * NOUT + c0] = make_float2(acc[i][j][2], acc[i][j][3]);
            float s0 = sas[c0], s1 = sas[c0 + 1], d0 = sad[c0], d1 = sad[c0 + 1];
            psl += acc[i][j][0] * s0 + acc[i][j][1] * s1;
            pdl += acc[i][j][0] * d0 + acc[i][j][1] * d1;
            psh += acc[i][j][2] * s0 + acc[i][j][3] * s1;
            pdh += acc[i][j][2] * d0 + acc[i][j][3] * d1;
        }
#pragma unroll
        for (int off = 1; off < 4; off <<= 1) {
            psl += __shfl_xor_sync(0xffffffffu, psl, off);
            pdl += __shfl_xor_sync(0xffffffffu, pdl, off);
            psh += __shfl_xor_sync(0xffffffffu, psh, off);
            pdh += __shfl_xor_sync(0xffffffffu, pdh, off);
        }
        if ((lane & 3) == 0) {
            int rowl = wm + i * 16 + gq;
            esp[wng * 128 + rowl] = psl;       edp[wng * 128 + rowl] = pdl;
            esp[wng * 128 + rowl + 8] = psh;   edp[wng * 128 + rowl + 8] = pdh;
        }
    }
    __syncthreads();
    if (tid < 128) {
        int r = r0 + tid;
        if (r < n) {
            g_es[r] = esp[tid] + esp[128 + tid] + esp[256 + tid] + esp[384 + tid];
            g_ed[r] = edp[tid] + edp[128 + tid] + edp[256 + tid] + edp[384 + tid];
        }
    }
}

// ---------------- GAT aggregation: one WARP per destination node ----------------
template <int C>
__global__ void k_agg(const float* __restrict__ bias, float* __restrict__ out) {
    float* __restrict__ outp = out ? out : (float*)g_h;
    int node = (blockIdx.x * blockDim.x + threadIdx.x) >> 5;
    int lane = threadIdx.x & 31;
    if (node >= NN) return;
    int beg = g_rowptr[node], end = g_rowptr[node + 1];
    int deg = end - beg;
    float edv = g_ed[node];

    constexpr int V = C / 32;
    float acc[V];
#pragma unroll
    for (int v = 0; v < V; v++) acc[v] = 0.f;
    float dp;

    if (deg <= 32) {
        int p = beg + lane;
        int s = 0;
        float al = -3.4e38f;
        if (p < end) {
            s = g_ssrc[p];
            float t = g_es[s] + edv;
            al = t > 0.f ? t : 0.2f * t;
        }
        float m = al;
#pragma unroll
        for (int off = 16; off; off >>= 1) m = fmaxf(m, __shfl_xor_sync(0xffffffffu, m, off));
        float w = (p < end) ? __expf(al - m) : 0.f;
        dp = w;
#pragma unroll
        for (int off = 16; off; off >>= 1) dp += __shfl_xor_sync(0xffffffffu, dp, off);

#pragma unroll 4
        for (int j = 0; j < deg; j++) {
            float wj = __shfl_sync(0xffffffffu, w, j);
            int   sj = __shfl_sync(0xffffffffu, s, j);
            if (V == 4) {
                float4 xv = *(const float4*)&g_xp[sj * C + lane * 4];
                acc[0] += wj * xv.x; acc[1] += wj * xv.y;
                acc[2] += wj * xv.z; acc[3] += wj * xv.w;
            } else {
                float2 xv = *(const float2*)&g_xp[sj * C + lane * 2];
                acc[0] += wj * xv.x; acc[1] += wj * xv.y;
            }
        }
    } else {
        float m = -3.4e38f;
        for (int p = beg + lane; p < end; p += 32) {
            float al = g_es[g_ssrc[p]] + edv;
            al = al > 0.f ? al : 0.2f * al;
            m = fmaxf(m, al);
        }
#pragma unroll
        for (int off = 16; off; off >>= 1) m = fmaxf(m, __shfl_xor_sync(0xffffffffu, m, off));

        dp = 0.f;
        for (int base = beg; base < end; base += 32) {
            int p = base + lane;
            float w = 0.f; int s = 0;
            if (p < end) {
                s = g_ssrc[p];
                float al = g_es[s] + edv;
                al = al > 0.f ? al : 0.2f * al;
                w = __expf(al - m);
                dp += w;
            }
            int cnt = min(32, end - base);
#pragma unroll 4
            for (int j = 0; j < cnt; j++) {
                float wj = __shfl_sync(0xffffffffu, w, j);
                int   sj = __shfl_sync(0xffffffffu, s, j);
                if (V == 4) {
                    float4 xv = *(const float4*)&g_xp[sj * C + lane * 4];
                    acc[0] += wj * xv.x; acc[1] += wj * xv.y;
                    acc[2] += wj * xv.z; acc[3] += wj * xv.w;
                } else {
                    float2 xv = *(const float2*)&g_xp[sj * C + lane * 2];
                    acc[0] += wj * xv.x; acc[1] += wj * xv.y;
                }
            }
        }
#pragma unroll
        for (int off = 16; off; off >>= 1) dp += __shfl_xor_sync(0xffffffffu, dp, off);
    }

    float inv = 1.f / dp;
    if (V == 4) {
        float4 b4 = *(const float4*)&bias[lane * 4];
        float4 o = make_float4(acc[0] * inv + b4.x, acc[1] * inv + b4.y,
                               acc[2] * inv + b4.z, acc[3] * inv + b4.w);
        *(float4*)&outp[node * C + lane * 4] = o;
    } else {
        float2 b2 = *(const float2*)&bias[lane * 2];
        float2 o = make_float2(acc[0] * inv + b2.x, acc[1] * inv + b2.y);
        *(float2*)&outp[node * C + lane * 2] = o;
    }
}

// ---------------- BatchNorm stats ----------------
__global__ void k_zero_stats() {
    int i = threadIdx.x;
    if (i < 2 * DHx) g_stats[i] = 0.f;
}
__global__ void k_bnstats(int n) {
    int c = threadIdx.x;
    float s = 0.f, sq = 0.f;
    for (int r = blockIdx.x; r < n; r += gridDim.x) {
        float v = g_h[r * 128 + c];
        s += v; sq += v * v;
    }
    atomicAdd(&g_stats[c], s);
    atomicAdd(&g_stats[128 + c], sq);
}
__global__ void k_bnparams(const float* __restrict__ g, const float* __restrict__ be, int n) {
    int c = threadIdx.x;
    float inv_n = 1.f / (float)n;
    float m = g_stats[c] * inv_n;
    float v = g_stats[128 + c] * inv_n - m * m;
    float scv = g[c] * rsqrtf(v + 1e-5f);
    g_scale[c] = scv;
    g_shift[c] = be[c] - m * scv;
}

// ---------------- pooling ----------------
__global__ void k_zero_pool() {
    int i = blockIdx.x * blockDim.x + threadIdx.x;
    if (i < NGx * DOUTx) g_pool[i] = 0.f;
}
__global__ void k_pool(const float* __restrict__ gp, const float* __restrict__ hn, int n) {
    __shared__ float gpt[32][129];
    __shared__ float hnt[32][65];
    int tid = threadIdx.x;
    int tn = (tid & 15) * 4;
    int tm = (tid >> 4) * 8;
    float acc[8][4];
#pragma unroll
    for (int a = 0; a < 8; a++)
#pragma unroll
        for (int b = 0; b < 4; b++) acc[a][b] = 0.f;

    int kpb  = (n + gridDim.x - 1) / gridDim.x;
    int kbeg = blockIdx.x * kpb;
    int kend = min(n, kbeg + kpb);

    for (int k0 = kbeg; k0 < kend; k0 += 32) {
        int kt = min(32, kend - k0);
        for (int l = tid; l < 128 * 32; l += 256) {
            int m = l >> 5, kk = l & 31;
            gpt[kk][m] = (kk < kt) ? gp[m * n + k0 + kk] : 0.f;
        }
        for (int l = tid; l < 32 * 64; l += 256) {
            int kk = l >> 6, cc = l & 63;
            hnt[kk][cc] = (kk < kt) ? hn[(k0 + kk) * 64 + cc] : 0.f;
        }
        __syncthreads();
#pragma unroll 4
        for (int kk = 0; kk < 32; kk++) {
            float h0 = hnt[kk][tn + 0], h1 = hnt[kk][tn + 1];
            float h2 = hnt[kk][tn + 2], h3 = hnt[kk][tn + 3];
#pragma unroll
            for (int a = 0; a < 8; a++) {
                float g = gpt[kk][tm + a];
                acc[a][0] += g * h0;
                acc[a][1] += g * h1;
                acc[a][2] += g * h2;
                acc[a][3] += g * h3;
            }
        }
        __syncthreads();
    }
#pragma unroll
    for (int a = 0; a < 8; a++)
#pragma unroll
        for (int b = 0; b < 4; b++)
            atomicAdd(&g_pool[(tm + a) * 64 + tn + b], acc[a][b]);
}
__global__ void k_copy_pool(float* __restrict__ out) {
    int i = blockIdx.x * blockDim.x + threadIdx.x;
    if (i < NGx * DOUTx) out[i] = g_pool[i];
}

// ---------------- launch ----------------
extern "C" void kernel_launch(void* const* d_in, const int* in_sizes, int n_in,
                              void* d_out, int out_size) {
    const float* x   = (const float*)d_in[0];
    const void*  ei  = (const void*)d_in[1];
    const float* gp  = (const float*)d_in[2];
    const float* W1  = (const float*)d_in[3];
    const float* as1 = (const float*)d_in[4];
    const float* ad1 = (const float*)d_in[5];
    const float* b1  = (const float*)d_in[6];
    const float* g1  = (const float*)d_in[7];
    const float* be1 = (const float*)d_in[8];
    const float* W2  = (const float*)d_in[9];
    const float* as2 = (const float*)d_in[10];
    const float* ad2 = (const float*)d_in[11];
    const float* b2  = (const float*)d_in[12];
    const float* g2  = (const float*)d_in[13];
    const float* be2 = (const float*)d_in[14];
    const float* W3  = (const float*)d_in[15];
    const float* as3 = (const float*)d_in[16];
    const float* ad3 = (const float*)d_in[17];
    const float* b3  = (const float*)d_in[18];

    float* out       = (float*)d_out;
    float* out_pool  = out;                    // [128,64]
    float* out_nodes = out + NGx * DOUTx;      // [50000,64]

    const int T = 256;
    const int PAD = 136;
    const int SM128 = 6144 + 4 * 128 * PAD * 2;                 // 145408
    const int SM64  = 6144 + 2 * 128 * PAD * 2 + 2 * 64 * PAD * 2;   // 110592
    cudaFuncSetAttribute((const void*)k_gemm_mma<128, false>, cudaFuncAttributeMaxDynamicSharedMemorySize, SM128);
    cudaFuncSetAttribute((const void*)k_gemm_mma<128, true>,  cudaFuncAttributeMaxDynamicSharedMemorySize, SM128);
    cudaFuncSetAttribute((const void*)k_gemm_mma<64, true>,   cudaFuncAttributeMaxDynamicSharedMemorySize, SM64);

    int gemm_blocks = (NN + 127) / 128;
    int warp_blocks = (NN * 32 + T - 1) / T;

    // keep GEMM-1 at launch index 3 (ncu's profiled slot)
    k_detect<<<1, 256>>>((const unsigned int*)ei);
    k_zero_cnt<<<(NN + T - 1) / T, T>>>();
    k_prepw<128><<<64, 256>>>(W1);
    k_gemm_mma<128, false><<<gemm_blocks, 256, SM128>>>(x, as1, ad1, NN);   // <- profiled

    // CSR build
    k_hist<<<(ETOT + T - 1) / T, T>>>(ei);
    k_scan1<<<49, 1024>>>();
    k_scan2<<<1, 64>>>();
    k_scan3<<<49, 1024>>>();
    k_scatter<<<(ETOT + T - 1) / T, T>>>(ei);

    // ---- Layer 1 agg + BN ----
    k_agg<128><<<warp_blocks, T>>>(b1, nullptr);
    k_zero_stats<<<1, 256>>>();
    k_bnstats<<<512, 128>>>(NN);
    k_bnparams<<<1, 128>>>(g1, be1, NN);

    // ---- Layer 2 ----
    k_prepw<128><<<64, 256>>>(W2);
    k_gemm_mma<128, true><<<gemm_blocks, 256, SM128>>>(nullptr, as2, ad2, NN);
    k_agg<128><<<warp_blocks, T>>>(b2, nullptr);
    k_zero_stats<<<1, 256>>>();
    k_bnstats<<<512, 128>>>(NN);
    k_bnparams<<<1, 128>>>(g2, be2, NN);

    // ---- Layer 3 ----
    k_prepw<64><<<32, 256>>>(W3);
    k_gemm_mma<64, true><<<gemm_blocks, 256, SM64>>>(nullptr, as3, ad3, NN);
    k_agg<64><<<warp_blocks, T>>>(b3, out_nodes);

    // ---- pooling ----
    k_zero_pool<<<(NGx * DOUTx + T - 1) / T, T>>>();
    k_pool<<<128, 256>>>(gp, out_nodes, NN);
    k_copy_pool<<<(NGx * DOUTx + T - 1) / T, T>>>(out_pool);
}

// round 8
// speedup vs baseline: 1.7311x; 1.0114x over previous
#include <cuda_runtime.h>
#include <cuda_bf16.h>
#include <cstdint>

#define NN   50000
#define EE   800000
#define ETOT (EE + NN)
#define DHx  128
#define DOUTx 64
#define NGx  128

// ---------------- device scratch ----------------
__device__ int   g_is64;
__device__ int   g_cnt[NN];
__device__ int   g_btot[64];
__device__ int   g_boff[64];
__device__ int   g_rowptr[NN + 1];
__device__ int   g_cur[NN];
__device__ int   g_ssrc[ETOT];
__device__ float g_xp[NN * DHx];
__device__ float g_h [NN * DHx];
__device__ float g_es[NN];
__device__ float g_ed[NN];
__device__ float g_stats[2 * DHx];
__device__ float g_scale[DHx];
__device__ float g_shift[DHx];
__device__ float g_pool[NGx * DOUTx];
__device__ __nv_bfloat16 g_bhi[128 * 128];   // W^T hi split [n][k]
__device__ __nv_bfloat16 g_blo[128 * 128];   // W^T lo split

__device__ __forceinline__ uint32_t pack_bf2(float a, float b) {
    __nv_bfloat162 t = __floats2bfloat162_rn(a, b);
    return *(uint32_t*)&t;
}

__device__ __forceinline__ void mma_bf16(float* c, uint32_t a0, uint32_t a1, uint32_t a2,
                                         uint32_t a3, uint32_t b0, uint32_t b1) {
    asm volatile(
        "mma.sync.aligned.m16n8k16.row.col.f32.bf16.bf16.f32 "
        "{%0,%1,%2,%3},{%4,%5,%6,%7},{%8,%9},{%0,%1,%2,%3};"
        : "+f"(c[0]), "+f"(c[1]), "+f"(c[2]), "+f"(c[3])
        : "r"(a0), "r"(a1), "r"(a2), "r"(a3), "r"(b0), "r"(b1));
}

// ---------------- edge dtype detection ----------------
__global__ void k_detect(const unsigned int* __restrict__ ei_raw) {
    __shared__ unsigned int sh[256];
    int t = threadIdx.x;
    unsigned int v = 0;
    for (int i = t; i < 1024; i += 256) v |= ei_raw[2 * i + 1];
    sh[t] = v;
    __syncthreads();
    for (int off = 128; off; off >>= 1) {
        if (t < off) sh[t] |= sh[t + off];
        __syncthreads();
    }
    if (t == 0) g_is64 = (sh[0] == 0) ? 1 : 0;
}

__device__ __forceinline__ int edge_at(const void* ei, int idx) {
    int v;
    if (g_is64) v = (int)((const long long*)ei)[idx];
    else        v = ((const int*)ei)[idx];
    v = v < 0 ? 0 : (v >= NN ? NN - 1 : v);
    return v;
}

// ---------------- CSR build ----------------
__global__ void k_zero_cnt() {
    int i = blockIdx.x * blockDim.x + threadIdx.x;
    if (i < NN) g_cnt[i] = 0;
}
__global__ void k_hist(const void* __restrict__ ei) {
    int e = blockIdx.x * blockDim.x + threadIdx.x;
    if (e >= ETOT) return;
    int dst = (e < EE) ? edge_at(ei, EE + e) : (e - EE);
    atomicAdd(&g_cnt[dst], 1);
}
__global__ void k_scan1() {
    int t = threadIdx.x;
    int i = blockIdx.x * 1024 + t;
    int v = (i < NN) ? g_cnt[i] : 0;
    __shared__ int sh[1024];
    sh[t] = v;
    __syncthreads();
    for (int off = 1; off < 1024; off <<= 1) {
        int a = (t >= off) ? sh[t - off] : 0;
        __syncthreads();
        sh[t] += a;
        __syncthreads();
    }
    if (i < NN) g_cnt[i] = sh[t] - v;
    if (t == 1023) g_btot[blockIdx.x] = sh[1023];
}
__global__ void k_scan2() {
    int t = threadIdx.x;
    int v = (t < 49) ? g_btot[t] : 0;
    __shared__ int sh[64];
    sh[t] = v;
    __syncthreads();
    for (int off = 1; off < 64; off <<= 1) {
        int a = (t >= off) ? sh[t - off] : 0;
        __syncthreads();
        sh[t] += a;
        __syncthreads();
    }
    if (t < 49) g_boff[t] = sh[t] - v;
}
__global__ void k_scan3() {
    int i = blockIdx.x * 1024 + threadIdx.x;
    if (i < NN) {
        int rp = g_cnt[i] + g_boff[blockIdx.x];
        g_rowptr[i] = rp;
        g_cur[i] = rp;
    }
    if (i == 0) g_rowptr[NN] = ETOT;
}
__global__ void k_scatter(const void* __restrict__ ei) {
    int e = blockIdx.x * blockDim.x + threadIdx.x;
    if (e >= ETOT) return;
    int s, d;
    if (e < EE) { s = edge_at(ei, e); d = edge_at(ei, EE + e); }
    else        { s = e - EE;         d = s; }
    int pos = atomicAdd(&g_cur[d], 1);
    g_ssrc[pos] = s;
}

// ---------------- W prep: transpose + bf16 hi/lo split ----------------
template <int NOUT>
__global__ void k_prepw(const float* __restrict__ W) {
    int i = blockIdx.x * blockDim.x + threadIdx.x;
    if (i >= NOUT * 128) return;
    int nrow = i >> 7, k = i & 127;            // B[n][k] = W[k][n]
    float w = W[k * NOUT + nrow];
    __nv_bfloat16 h = __float2bfloat16_rn(w);
    g_bhi[i] = h;
    g_blo[i] = __float2bfloat16_rn(w - __bfloat162float(h));
}

// ---------------- warp-MMA GEMM: 64 x NOUT tile, K=128, 3-term bf16 split --------
// B (W^T hi/lo) read straight from global (L1/L2 hot); only A staged in smem.
// smem: 0 sas(512) 512 sad(512) 1024 sc(512) 1536 sf(512) 2048 esp(1024) 3072 edp(1024)
//       4096 A_hi (64xPAD bf16) then A_lo
template <int NOUT, bool BN>
__global__ void __launch_bounds__(256, 3) k_gemm_mma(const float* __restrict__ A,
                                                     const float* __restrict__ asv,
                                                     const float* __restrict__ adv, int n) {
    extern __shared__ char smem[];
    const float* __restrict__ Ap = BN ? (const float*)g_h : A;
    constexpr int PAD = 136;
    constexpr int ASZ = 64 * PAD;
    float* sas = (float*)(smem);
    float* sad = (float*)(smem + 512);
    float* sc  = (float*)(smem + 1024);
    float* sf  = (float*)(smem + 1536);
    float* esp = (float*)(smem + 2048);
    float* edp = (float*)(smem + 3072);
    __nv_bfloat16* ah = (__nv_bfloat16*)(smem + 4096);
    __nv_bfloat16* al = ah + ASZ;

    int tid = threadIdx.x, wid = tid >> 5, lane = tid & 31;
    int r0 = blockIdx.x * 64;

    if (tid < NOUT) { sas[tid] = asv[tid]; sad[tid] = adv[tid]; }
    if (BN && tid < 128) { sc[tid] = g_scale[tid]; sf[tid] = g_shift[tid]; }
    if (BN) __syncthreads();

    // A tile fp32 -> bf16 hi/lo (fused BN+ReLU); 64 rows x 128 cols
    for (int l = tid; l < 64 * 32; l += 256) {
        int row = l >> 5, k = (l & 31) << 2;
        float4 v = make_float4(0.f, 0.f, 0.f, 0.f);
        if (r0 + row < n) v = *(const float4*)&Ap[(r0 + row) * 128 + k];
        if (BN) {
            v.x = fmaxf(v.x * sc[k + 0] + sf[k + 0], 0.f);
            v.y = fmaxf(v.y * sc[k + 1] + sf[k + 1], 0.f);
            v.z = fmaxf(v.z * sc[k + 2] + sf[k + 2], 0.f);
            v.w = fmaxf(v.w * sc[k + 3] + sf[k + 3], 0.f);
        }
        float h0 = __bfloat162float(__float2bfloat16_rn(v.x));
        float h1 = __bfloat162float(__float2bfloat16_rn(v.y));
        float h2 = __bfloat162float(__float2bfloat16_rn(v.z));
        float h3 = __bfloat162float(__float2bfloat16_rn(v.w));
        *(uint2*)&ah[row * PAD + k] = make_uint2(pack_bf2(v.x, v.y), pack_bf2(v.z, v.w));
        *(uint2*)&al[row * PAD + k] = make_uint2(pack_bf2(v.x - h0, v.y - h1),
                                                 pack_bf2(v.z - h2, v.w - h3));
    }
    __syncthreads();

    constexpr int WN = (NOUT == 128) ? 32 : 16;      // warp n-width
    constexpr int NA = WN / 8;
    int wm = (wid & 1) * 32;
    int wn = (wid >> 1) * WN;
    int gq = lane >> 2, t2 = (lane & 3) * 2;

    float acc[2][NA][4];
#pragma unroll
    for (int i = 0; i < 2; i++)
#pragma unroll
        for (int j = 0; j < NA; j++)
#pragma unroll
            for (int q = 0; q < 4; q++) acc[i][j][q] = 0.f;

#pragma unroll
    for (int ks = 0; ks < 8; ks++) {
        int k0 = ks * 16;
        uint32_t fbh[NA][2], fbl[NA][2];
#pragma unroll
        for (int j = 0; j < NA; j++) {
            const __nv_bfloat16* pb = &g_bhi[(wn + j * 8 + gq) * 128 + k0 + t2];
            fbh[j][0] = *(const uint32_t*)pb;
            fbh[j][1] = *(const uint32_t*)(pb + 8);
            const __nv_bfloat16* pl = &g_blo[(wn + j * 8 + gq) * 128 + k0 + t2];
            fbl[j][0] = *(const uint32_t*)pl;
            fbl[j][1] = *(const uint32_t*)(pl + 8);
        }
#pragma unroll
        for (int i = 0; i < 2; i++) {
            const __nv_bfloat16* pa = &ah[(wm + i * 16 + gq) * PAD + k0 + t2];
            uint32_t ah0 = *(const uint32_t*)pa;
            uint32_t ah1 = *(const uint32_t*)(pa + 8 * PAD);
            uint32_t ah2 = *(const uint32_t*)(pa + 8);
            uint32_t ah3 = *(const uint32_t*)(pa + 8 * PAD + 8);
            const __nv_bfloat16* qa = &al[(wm + i * 16 + gq) * PAD + k0 + t2];
            uint32_t al0 = *(const uint32_t*)qa;
            uint32_t al1 = *(const uint32_t*)(qa + 8 * PAD);
            uint32_t al2 = *(const uint32_t*)(qa + 8);
            uint32_t al3 = *(const uint32_t*)(qa + 8 * PAD + 8);
#pragma unroll
            for (int j = 0; j < NA; j++) {
                mma_bf16(acc[i][j], ah0, ah1, ah2, ah3, fbh[j][0], fbh[j][1]);
                mma_bf16(acc[i][j], ah0, ah1, ah2, ah3, fbl[j][0], fbl[j][1]);
                mma_bf16(acc[i][j], al0, al1, al2, al3, fbh[j][0], fbh[j][1]);
            }
        }
    }

    // epilogue: store xp + fused attention dot partials
    int wng = wid >> 1;                          // 0..3 column group
#pragma unroll
    for (int i = 0; i < 2; i++) {
        int rl = r0 + wm + i * 16 + gq;
        int rh = rl + 8;
        float psl = 0.f, pdl = 0.f, psh = 0.f, pdh = 0.f;
#pragma unroll
        for (int j = 0; j < NA; j++) {
            int c0 = wn + j * 8 + t2;
            if (rl < n) *(float2*)&g_xp[rl * NOUT + c0] = make_float2(acc[i][j][0], acc[i][j][1]);
            if (rh < n) *(float2*)&g_xp[rh * NOUT + c0] = make_float2(acc[i][j][2], acc[i][j][3]);
            float s0 = sas[c0], s1 = sas[c0 + 1], d0 = sad[c0], d1 = sad[c0 + 1];
            psl += acc[i][j][0] * s0 + acc[i][j][1] * s1;
            pdl += acc[i][j][0] * d0 + acc[i][j][1] * d1;
            psh += acc[i][j][2] * s0 + acc[i][j][3] * s1;
            pdh += acc[i][j][2] * d0 + acc[i][j][3] * d1;
        }
#pragma unroll
        for (int off = 1; off < 4; off <<= 1) {
            psl += __shfl_xor_sync(0xffffffffu, psl, off);
            pdl += __shfl_xor_sync(0xffffffffu, pdl, off);
            psh += __shfl_xor_sync(0xffffffffu, psh, off);
            pdh += __shfl_xor_sync(0xffffffffu, pdh, off);
        }
        if ((lane & 3) == 0) {
            int rowl = wm + i * 16 + gq;
            esp[wng * 64 + rowl] = psl;       edp[wng * 64 + rowl] = pdl;
            esp[wng * 64 + rowl + 8] = psh;   edp[wng * 64 + rowl + 8] = pdh;
        }
    }
    __syncthreads();
    if (tid < 64) {
        int r = r0 + tid;
        if (r < n) {
            g_es[r] = esp[tid] + esp[64 + tid] + esp[128 + tid] + esp[192 + tid];
            g_ed[r] = edp[tid] + edp[64 + tid] + edp[128 + tid] + edp[192 + tid];
        }
    }
}

// ---------------- GAT aggregation: one WARP per destination node ----------------
template <int C>
__global__ void k_agg(const float* __restrict__ bias, float* __restrict__ out) {
    float* __restrict__ outp = out ? out : (float*)g_h;
    int node = (blockIdx.x * blockDim.x + threadIdx.x) >> 5;
    int lane = threadIdx.x & 31;
    if (node >= NN) return;
    int beg = g_rowptr[node], end = g_rowptr[node + 1];
    int deg = end - beg;
    float edv = g_ed[node];

    constexpr int V = C / 32;
    float acc[V];
#pragma unroll
    for (int v = 0; v < V; v++) acc[v] = 0.f;
    float dp;

    if (deg <= 32) {
        int p = beg + lane;
        int s = 0;
        float al = -3.4e38f;
        if (p < end) {
            s = g_ssrc[p];
            float t = g_es[s] + edv;
            al = t > 0.f ? t : 0.2f * t;
        }
        float m = al;
#pragma unroll
        for (int off = 16; off; off >>= 1) m = fmaxf(m, __shfl_xor_sync(0xffffffffu, m, off));
        float w = (p < end) ? __expf(al - m) : 0.f;
        dp = w;
#pragma unroll
        for (int off = 16; off; off >>= 1) dp += __shfl_xor_sync(0xffffffffu, dp, off);

#pragma unroll 4
        for (int j = 0; j < deg; j++) {
            float wj = __shfl_sync(0xffffffffu, w, j);
            int   sj = __shfl_sync(0xffffffffu, s, j);
            if (V == 4) {
                float4 xv = *(const float4*)&g_xp[sj * C + lane * 4];
                acc[0] += wj * xv.x; acc[1] += wj * xv.y;
                acc[2] += wj * xv.z; acc[3] += wj * xv.w;
            } else {
                float2 xv = *(const float2*)&g_xp[sj * C + lane * 2];
                acc[0] += wj * xv.x; acc[1] += wj * xv.y;
            }
        }
    } else {
        float m = -3.4e38f;
        for (int p = beg + lane; p < end; p += 32) {
            float al = g_es[g_ssrc[p]] + edv;
            al = al > 0.f ? al : 0.2f * al;
            m = fmaxf(m, al);
        }
#pragma unroll
        for (int off = 16; off; off >>= 1) m = fmaxf(m, __shfl_xor_sync(0xffffffffu, m, off));

        dp = 0.f;
        for (int base = beg; base < end; base += 32) {
            int p = base + lane;
            float w = 0.f; int s = 0;
            if (p < end) {
                s = g_ssrc[p];
                float al = g_es[s] + edv;
                al = al > 0.f ? al : 0.2f * al;
                w = __expf(al - m);
                dp += w;
            }
            int cnt = min(32, end - base);
#pragma unroll 4
            for (int j = 0; j < cnt; j++) {
                float wj = __shfl_sync(0xffffffffu, w, j);
                int   sj = __shfl_sync(0xffffffffu, s, j);
                if (V == 4) {
                    float4 xv = *(const float4*)&g_xp[sj * C + lane * 4];
                    acc[0] += wj * xv.x; acc[1] += wj * xv.y;
                    acc[2] += wj * xv.z; acc[3] += wj * xv.w;
                } else {
                    float2 xv = *(const float2*)&g_xp[sj * C + lane * 2];
                    acc[0] += wj * xv.x; acc[1] += wj * xv.y;
                }
            }
        }
#pragma unroll
        for (int off = 16; off; off >>= 1) dp += __shfl_xor_sync(0xffffffffu, dp, off);
    }

    float inv = 1.f / dp;
    if (V == 4) {
        float4 b4 = *(const float4*)&bias[lane * 4];
        float4 o = make_float4(acc[0] * inv + b4.x, acc[1] * inv + b4.y,
                               acc[2] * inv + b4.z, acc[3] * inv + b4.w);
        *(float4*)&outp[node * C + lane * 4] = o;
    } else {
        float2 b2 = *(const float2*)&bias[lane * 2];
        float2 o = make_float2(acc[0] * inv + b2.x, acc[1] * inv + b2.y);
        *(float2*)&outp[node * C + lane * 2] = o;
    }
}

// ---------------- BatchNorm stats ----------------
__global__ void k_zero_stats() {
    int i = threadIdx.x;
    if (i < 2 * DHx) g_stats[i] = 0.f;
}
__global__ void k_bnstats(int n) {
    int c = threadIdx.x;
    float s = 0.f, sq = 0.f;
    for (int r = blockIdx.x; r < n; r += gridDim.x) {
        float v = g_h[r * 128 + c];
        s += v; sq += v * v;
    }
    atomicAdd(&g_stats[c], s);
    atomicAdd(&g_stats[128 + c], sq);
}
__global__ void k_bnparams(const float* __restrict__ g, const float* __restrict__ be, int n) {
    int c = threadIdx.x;
    float inv_n = 1.f / (float)n;
    float m = g_stats[c] * inv_n;
    float v = g_stats[128 + c] * inv_n - m * m;
    float scv = g[c] * rsqrtf(v + 1e-5f);
    g_scale[c] = scv;
    g_shift[c] = be[c] - m * scv;
}

// ---------------- pooling ----------------
__global__ void k_zero_pool() {
    int i = blockIdx.x * blockDim.x + threadIdx.x;
    if (i < NGx * DOUTx) g_pool[i] = 0.f;
}
__global__ void k_pool(const float* __restrict__ gp, const float* __restrict__ hn, int n) {
    __shared__ float gpt[32][129];
    __shared__ float hnt[32][65];
    int tid = threadIdx.x;
    int tn = (tid & 15) * 4;
    int tm = (tid >> 4) * 8;
    float acc[8][4];
#pragma unroll
    for (int a = 0; a < 8; a++)
#pragma unroll
        for (int b = 0; b < 4; b++) acc[a][b] = 0.f;

    int kpb  = (n + gridDim.x - 1) / gridDim.x;
    int kbeg = blockIdx.x * kpb;
    int kend = min(n, kbeg + kpb);

    for (int k0 = kbeg; k0 < kend; k0 += 32) {
        int kt = min(32, kend - k0);
        for (int l = tid; l < 128 * 32; l += 256) {
            int m = l >> 5, kk = l & 31;
            gpt[kk][m] = (kk < kt) ? gp[m * n + k0 + kk] : 0.f;
        }
        for (int l = tid; l < 32 * 64; l += 256) {
            int kk = l >> 6, cc = l & 63;
            hnt[kk][cc] = (kk < kt) ? hn[(k0 + kk) * 64 + cc] : 0.f;
        }
        __syncthreads();
#pragma unroll 4
        for (int kk = 0; kk < 32; kk++) {
            float h0 = hnt[kk][tn + 0], h1 = hnt[kk][tn + 1];
            float h2 = hnt[kk][tn + 2], h3 = hnt[kk][tn + 3];
#pragma unroll
            for (int a = 0; a < 8; a++) {
                float g = gpt[kk][tm + a];
                acc[a][0] += g * h0;
                acc[a][1] += g * h1;
                acc[a][2] += g * h2;
                acc[a][3] += g * h3;
            }
        }
        __syncthreads();
    }
#pragma unroll
    for (int a = 0; a < 8; a++)
#pragma unroll
        for (int b = 0; b < 4; b++)
            atomicAdd(&g_pool[(tm + a) * 64 + tn + b], acc[a][b]);
}
__global__ void k_copy_pool(float* __restrict__ out) {
    int i = blockIdx.x * blockDim.x + threadIdx.x;
    if (i < NGx * DOUTx) out[i] = g_pool[i];
}

// ---------------- launch ----------------
extern "C" void kernel_launch(void* const* d_in, const int* in_sizes, int n_in,
                              void* d_out, int out_size) {
    const float* x   = (const float*)d_in[0];
    const void*  ei  = (const void*)d_in[1];
    const float* gp  = (const float*)d_in[2];
    const float* W1  = (const float*)d_in[3];
    const float* as1 = (const float*)d_in[4];
    const float* ad1 = (const float*)d_in[5];
    const float* b1  = (const float*)d_in[6];
    const float* g1  = (const float*)d_in[7];
    const float* be1 = (const float*)d_in[8];
    const float* W2  = (const float*)d_in[9];
    const float* as2 = (const float*)d_in[10];
    const float* ad2 = (const float*)d_in[11];
    const float* b2  = (const float*)d_in[12];
    const float* g2  = (const float*)d_in[13];
    const float* be2 = (const float*)d_in[14];
    const float* W3  = (const float*)d_in[15];
    const float* as3 = (const float*)d_in[16];
    const float* ad3 = (const float*)d_in[17];
    const float* b3  = (const float*)d_in[18];

    float* out       = (float*)d_out;
    float* out_pool  = out;                    // [128,64]
    float* out_nodes = out + NGx * DOUTx;      // [50000,64]

    const int T = 256;
    const int PAD = 136;
    const int SMA = 4096 + 2 * 64 * PAD * 2;   // 38912
    cudaFuncSetAttribute((const void*)k_gemm_mma<128, false>, cudaFuncAttributeMaxDynamicSharedMemorySize, SMA);
    cudaFuncSetAttribute((const void*)k_gemm_mma<128, true>,  cudaFuncAttributeMaxDynamicSharedMemorySize, SMA);
    cudaFuncSetAttribute((const void*)k_gemm_mma<64, true>,   cudaFuncAttributeMaxDynamicSharedMemorySize, SMA);

    int gemm_blocks = (NN + 63) / 64;          // 782
    int warp_blocks = (NN * 32 + T - 1) / T;

    // keep GEMM-1 at launch index 3 (ncu's profiled slot)
    k_detect<<<1, 256>>>((const unsigned int*)ei);
    k_zero_cnt<<<(NN + T - 1) / T, T>>>();
    k_prepw<128><<<64, 256>>>(W1);
    k_gemm_mma<128, false><<<gemm_blocks, 256, SMA>>>(x, as1, ad1, NN);   // <- profiled

    // CSR build
    k_hist<<<(ETOT + T - 1) / T, T>>>(ei);
    k_scan1<<<49, 1024>>>();
    k_scan2<<<1, 64>>>();
    k_scan3<<<49, 1024>>>();
    k_scatter<<<(ETOT + T - 1) / T, T>>>(ei);

    // ---- Layer 1 agg + BN ----
    k_agg<128><<<warp_blocks, T>>>(b1, nullptr);
    k_zero_stats<<<1, 256>>>();
    k_bnstats<<<512, 128>>>(NN);
    k_bnparams<<<1, 128>>>(g1, be1, NN);

    // ---- Layer 2 ----
    k_prepw<128><<<64, 256>>>(W2);
    k_gemm_mma<128, true><<<gemm_blocks, 256, SMA>>>(nullptr, as2, ad2, NN);
    k_agg<128><<<warp_blocks, T>>>(b2, nullptr);
    k_zero_stats<<<1, 256>>>();
    k_bnstats<<<512, 128>>>(NN);
    k_bnparams<<<1, 128>>>(g2, be2, NN);

    // ---- Layer 3 ----
    k_prepw<64><<<32, 256>>>(W3);
    k_gemm_mma<64, true><<<gemm_blocks, 256, SMA>>>(nullptr, as3, ad3, NN);
    k_agg<64><<<warp_blocks, T>>>(b3, out_nodes);

    // ---- pooling ----
    k_zero_pool<<<(NGx * DOUTx + T - 1) / T, T>>>();
    k_pool<<<128, 256>>>(gp, out_nodes, NN);
    k_copy_pool<<<(NGx * DOUTx + T - 1) / T, T>>>(out_pool);
}

// round 9
// speedup vs baseline: 1.9661x; 1.1357x over previous
#include <cuda_runtime.h>
#include <cuda_bf16.h>
#include <cstdint>

#define NN   50000
#define EE   800000
#define ETOT (EE + NN)
#define DHx  128
#define DOUTx 64
#define NGx  128

// ---------------- device scratch ----------------
__device__ int   g_is64;
__device__ int   g_cnt[NN];
__device__ int   g_btot[64];
__device__ int   g_boff[64];
__device__ int   g_rowptr[NN + 1];
__device__ int   g_cur[NN];
__device__ int   g_ssrc[ETOT];
__device__ float g_xp[NN * DHx];
__device__ float g_h [NN * DHx];
__device__ float g_es[NN];
__device__ float g_ed[NN];
__device__ float g_stats[2 * DHx];
__device__ float g_scale[DHx];
__device__ float g_shift[DHx];
__device__ uint4 g_bpk[4096];      // fragment-packed W^T hi/lo: [n][ks][t2g] 16B

__device__ __forceinline__ uint32_t pack_bf2(float a, float b) {
    __nv_bfloat162 t = __floats2bfloat162_rn(a, b);
    return *(uint32_t*)&t;
}

__device__ __forceinline__ void mma_bf16(float* c, uint32_t a0, uint32_t a1, uint32_t a2,
                                         uint32_t a3, uint32_t b0, uint32_t b1) {
    asm volatile(
        "mma.sync.aligned.m16n8k16.row.col.f32.bf16.bf16.f32 "
        "{%0,%1,%2,%3},{%4,%5,%6,%7},{%8,%9},{%0,%1,%2,%3};"
        : "+f"(c[0]), "+f"(c[1]), "+f"(c[2]), "+f"(c[3])
        : "r"(a0), "r"(a1), "r"(a2), "r"(a3), "r"(b0), "r"(b1));
}

// ---------------- edge dtype detection ----------------
__global__ void k_detect(const unsigned int* __restrict__ ei_raw) {
    __shared__ unsigned int sh[256];
    int t = threadIdx.x;
    unsigned int v = 0;
    for (int i = t; i < 1024; i += 256) v |= ei_raw[2 * i + 1];
    sh[t] = v;
    __syncthreads();
    for (int off = 128; off; off >>= 1) {
        if (t < off) sh[t] |= sh[t + off];
        __syncthreads();
    }
    if (t == 0) g_is64 = (sh[0] == 0) ? 1 : 0;
}

__device__ __forceinline__ int edge_at(const void* ei, int idx) {
    int v;
    if (g_is64) v = (int)((const long long*)ei)[idx];
    else        v = ((const int*)ei)[idx];
    v = v < 0 ? 0 : (v >= NN ? NN - 1 : v);
    return v;
}

// ---------------- CSR build ----------------
__global__ void k_zero_cnt() {
    int i = blockIdx.x * blockDim.x + threadIdx.x;
    if (i < NN) g_cnt[i] = 0;
}
__global__ void k_hist(const void* __restrict__ ei) {
    int e = blockIdx.x * blockDim.x + threadIdx.x;
    if (e >= ETOT) return;
    int dst = (e < EE) ? edge_at(ei, EE + e) : (e - EE);
    atomicAdd(&g_cnt[dst], 1);
}
__global__ void k_scan1() {
    int t = threadIdx.x;
    int i = blockIdx.x * 1024 + t;
    int v = (i < NN) ? g_cnt[i] : 0;
    __shared__ int sh[1024];
    sh[t] = v;
    __syncthreads();
    for (int off = 1; off < 1024; off <<= 1) {
        int a = (t >= off) ? sh[t - off] : 0;
        __syncthreads();
        sh[t] += a;
        __syncthreads();
    }
    if (i < NN) g_cnt[i] = sh[t] - v;
    if (t == 1023) g_btot[blockIdx.x] = sh[1023];
}
__global__ void k_scan2() {
    int t = threadIdx.x;
    int v = (t < 49) ? g_btot[t] : 0;
    __shared__ int sh[64];
    sh[t] = v;
    __syncthreads();
    for (int off = 1; off < 64; off <<= 1) {
        int a = (t >= off) ? sh[t - off] : 0;
        __syncthreads();
        sh[t] += a;
        __syncthreads();
    }
    if (t < 49) g_boff[t] = sh[t] - v;
}
__global__ void k_scan3() {
    int i = blockIdx.x * 1024 + threadIdx.x;
    if (i < NN) {
        int rp = g_cnt[i] + g_boff[blockIdx.x];
        g_rowptr[i] = rp;
        g_cur[i] = rp;
    }
    if (i == 0) g_rowptr[NN] = ETOT;
}
__global__ void k_scatter(const void* __restrict__ ei) {
    int e = blockIdx.x * blockDim.x + threadIdx.x;
    if (e >= ETOT) return;
    int s, d;
    if (e < EE) { s = edge_at(ei, e); d = edge_at(ei, EE + e); }
    else        { s = e - EE;         d = s; }
    int pos = atomicAdd(&g_cur[d], 1);
    g_ssrc[pos] = s;
}

// ---------------- W prep: transpose + bf16 hi/lo split, fragment-packed ----------------
template <int NOUT>
__global__ void k_prepw(const float* __restrict__ W) {
    int i = blockIdx.x * blockDim.x + threadIdx.x;
    if (i >= NOUT * 32) return;
    int n = i >> 5, ks = (i >> 2) & 7, tg = i & 3;
    int ka = ks * 16 + tg * 2;
    int kb = ka + 8;
    float w00 = W[ka * NOUT + n],       w01 = W[(ka + 1) * NOUT + n];
    float w10 = W[kb * NOUT + n],       w11 = W[(kb + 1) * NOUT + n];
    float h00 = __bfloat162float(__float2bfloat16_rn(w00));
    float h01 = __bfloat162float(__float2bfloat16_rn(w01));
    float h10 = __bfloat162float(__float2bfloat16_rn(w10));
    float h11 = __bfloat162float(__float2bfloat16_rn(w11));
    uint4 v;
    v.x = pack_bf2(w00, w01);
    v.y = pack_bf2(w10, w11);
    v.z = pack_bf2(w00 - h00, w01 - h01);
    v.w = pack_bf2(w10 - h10, w11 - h11);
    g_bpk[i] = v;
}

// ---------------- warp-MMA GEMM: 64 x NOUT tile, K=128, 3-term bf16 split --------
// A pair-packed in smem (576B row stride, conflict-free LDS.128);
// B fragment-packed in global (LDG.128, coalesced, L1-hot).
// smem: 0 sas(512) 512 sad(512) 1024 sc(512) 1536 sf(512) 2048 esp(1024) 3072 edp(1024)
//       4096 ap: 64 rows x 576B
template <int NOUT, bool BN>
__global__ void __launch_bounds__(256, 3) k_gemm_mma(const float* __restrict__ A,
                                                     const float* __restrict__ asv,
                                                     const float* __restrict__ adv, int n) {
    extern __shared__ char smem[];
    const float* __restrict__ Ap = BN ? (const float*)g_h : A;
    constexpr int RSTR = 576;          // bytes per packed A row
    float* sas = (float*)(smem);
    float* sad = (float*)(smem + 512);
    float* sc  = (float*)(smem + 1024);
    float* sf  = (float*)(smem + 1536);
    float* esp = (float*)(smem + 2048);
    float* edp = (float*)(smem + 3072);
    char*  ap  = smem + 4096;

    int tid = threadIdx.x, wid = tid >> 5, lane = tid & 31;
    int r0 = blockIdx.x * 64;

    if (tid < NOUT) { sas[tid] = asv[tid]; sad[tid] = adv[tid]; }
    if (BN && tid < 128) { sc[tid] = g_scale[tid]; sf[tid] = g_shift[tid]; }
    if (BN) __syncthreads();

    // A tile fp32 -> bf16 hi/lo pair-packed (fused BN+ReLU)
    for (int l = tid; l < 64 * 32; l += 256) {
        int row = l >> 5, ks = (l >> 2) & 7, tg = l & 3;
        int ka = ks * 16 + tg * 2;
        int kb = ka + 8;
        float a0 = 0.f, a1 = 0.f, b0 = 0.f, b1 = 0.f;
        if (r0 + row < n) {
            float2 t = *(const float2*)&Ap[(r0 + row) * 128 + ka];
            a0 = t.x; a1 = t.y;
            float2 u = *(const float2*)&Ap[(r0 + row) * 128 + kb];
            b0 = u.x; b1 = u.y;
        }
        if (BN) {
            a0 = fmaxf(a0 * sc[ka] + sf[ka], 0.f);
            a1 = fmaxf(a1 * sc[ka + 1] + sf[ka + 1], 0.f);
            b0 = fmaxf(b0 * sc[kb] + sf[kb], 0.f);
            b1 = fmaxf(b1 * sc[kb + 1] + sf[kb + 1], 0.f);
        }
        float h0 = __bfloat162float(__float2bfloat16_rn(a0));
        float h1 = __bfloat162float(__float2bfloat16_rn(a1));
        float h2 = __bfloat162float(__float2bfloat16_rn(b0));
        float h3 = __bfloat162float(__float2bfloat16_rn(b1));
        uint4 v;
        v.x = pack_bf2(a0, a1);
        v.y = pack_bf2(b0, b1);
        v.z = pack_bf2(a0 - h0, a1 - h1);
        v.w = pack_bf2(b0 - h2, b1 - h3);
        *(uint4*)(ap + row * RSTR + ks * 64 + tg * 16) = v;
    }
    __syncthreads();

    constexpr int WN = (NOUT == 128) ? 32 : 16;
    constexpr int NA = WN / 8;
    int wm = (wid & 1) * 32;
    int wn = (wid >> 1) * WN;
    int gq = lane >> 2, tg = lane & 3, t2 = tg * 2;

    float acc[2][NA][4];
#pragma unroll
    for (int i = 0; i < 2; i++)
#pragma unroll
        for (int j = 0; j < NA; j++)
#pragma unroll
            for (int q = 0; q < 4; q++) acc[i][j][q] = 0.f;

#pragma unroll
    for (int ks = 0; ks < 8; ks++) {
        uint32_t fbh[NA][2], fbl[NA][2];
#pragma unroll
        for (int j = 0; j < NA; j++) {
            uint4 bv = g_bpk[(wn + j * 8 + gq) * 32 + ks * 4 + tg];
            fbh[j][0] = bv.x; fbh[j][1] = bv.y;
            fbl[j][0] = bv.z; fbl[j][1] = bv.w;
        }
#pragma unroll
        for (int i = 0; i < 2; i++) {
            int rl = wm + i * 16 + gq;
            uint4 av = *(uint4*)(ap + rl * RSTR + ks * 64 + tg * 16);
            uint4 aw = *(uint4*)(ap + (rl + 8) * RSTR + ks * 64 + tg * 16);
            // hi frags: a0=av.x a1=aw.x a2=av.y a3=aw.y ; lo: av.z/aw.z/av.w/aw.w
#pragma unroll
            for (int j = 0; j < NA; j++) {
                mma_bf16(acc[i][j], av.x, aw.x, av.y, aw.y, fbh[j][0], fbh[j][1]);
                mma_bf16(acc[i][j], av.x, aw.x, av.y, aw.y, fbl[j][0], fbl[j][1]);
                mma_bf16(acc[i][j], av.z, aw.z, av.w, aw.w, fbh[j][0], fbh[j][1]);
            }
        }
    }

    // epilogue: store xp + fused attention dot partials
    int wng = wid >> 1;
#pragma unroll
    for (int i = 0; i < 2; i++) {
        int rl = r0 + wm + i * 16 + gq;
        int rh = rl + 8;
        float psl = 0.f, pdl = 0.f, psh = 0.f, pdh = 0.f;
#pragma unroll
        for (int j = 0; j < NA; j++) {
            int c0 = wn + j * 8 + t2;
            if (rl < n) *(float2*)&g_xp[rl * NOUT + c0] = make_float2(acc[i][j][0], acc[i][j][1]);
            if (rh < n) *(float2*)&g_xp[rh * NOUT + c0] = make_float2(acc[i][j][2], acc[i][j][3]);
            float s0 = sas[c0], s1 = sas[c0 + 1], d0 = sad[c0], d1 = sad[c0 + 1];
            psl += acc[i][j][0] * s0 + acc[i][j][1] * s1;
            pdl += acc[i][j][0] * d0 + acc[i][j][1] * d1;
            psh += acc[i][j][2] * s0 + acc[i][j][3] * s1;
            pdh += acc[i][j][2] * d0 + acc[i][j][3] * d1;
        }
#pragma unroll
        for (int off = 1; off < 4; off <<= 1) {
            psl += __shfl_xor_sync(0xffffffffu, psl, off);
            pdl += __shfl_xor_sync(0xffffffffu, pdl, off);
            psh += __shfl_xor_sync(0xffffffffu, psh, off);
            pdh += __shfl_xor_sync(0xffffffffu, pdh, off);
        }
        if ((lane & 3) == 0) {
            int rowl = wm + i * 16 + gq;
            esp[wng * 64 + rowl] = psl;       edp[wng * 64 + rowl] = pdl;
            esp[wng * 64 + rowl + 8] = psh;   edp[wng * 64 + rowl + 8] = pdh;
        }
    }
    __syncthreads();
    if (tid < 64) {
        int r = r0 + tid;
        if (r < n) {
            g_es[r] = esp[tid] + esp[64 + tid] + esp[128 + tid] + esp[192 + tid];
            g_ed[r] = edp[tid] + edp[64 + tid] + edp[128 + tid] + edp[192 + tid];
        }
    }
}

// ---------------- GAT aggregation: one WARP per destination node ----------------
template <int C>
__global__ void k_agg(const float* __restrict__ bias, float* __restrict__ out) {
    float* __restrict__ outp = out ? out : (float*)g_h;
    int node = (blockIdx.x * blockDim.x + threadIdx.x) >> 5;
    int lane = threadIdx.x & 31;
    if (node >= NN) return;
    int beg = g_rowptr[node], end = g_rowptr[node + 1];
    int deg = end - beg;
    float edv = g_ed[node];

    constexpr int V = C / 32;
    float acc[V];
#pragma unroll
    for (int v = 0; v < V; v++) acc[v] = 0.f;
    float dp;

    if (deg <= 32) {
        int p = beg + lane;
        int s = 0;
        float al = -3.4e38f;
        if (p < end) {
            s = g_ssrc[p];
            float t = g_es[s] + edv;
            al = t > 0.f ? t : 0.2f * t;
        }
        float m = al;
#pragma unroll
        for (int off = 16; off; off >>= 1) m = fmaxf(m, __shfl_xor_sync(0xffffffffu, m, off));
        float w = (p < end) ? __expf(al - m) : 0.f;
        dp = w;
#pragma unroll
        for (int off = 16; off; off >>= 1) dp += __shfl_xor_sync(0xffffffffu, dp, off);

#pragma unroll 4
        for (int j = 0; j < deg; j++) {
            float wj = __shfl_sync(0xffffffffu, w, j);
            int   sj = __shfl_sync(0xffffffffu, s, j);
            if (V == 4) {
                float4 xv = *(const float4*)&g_xp[sj * C + lane * 4];
                acc[0] += wj * xv.x; acc[1] += wj * xv.y;
                acc[2] += wj * xv.z; acc[3] += wj * xv.w;
            } else {
                float2 xv = *(const float2*)&g_xp[sj * C + lane * 2];
                acc[0] += wj * xv.x; acc[1] += wj * xv.y;
            }
        }
    } else {
        float m = -3.4e38f;
        for (int p = beg + lane; p < end; p += 32) {
            float al = g_es[g_ssrc[p]] + edv;
            al = al > 0.f ? al : 0.2f * al;
            m = fmaxf(m, al);
        }
#pragma unroll
        for (int off = 16; off; off >>= 1) m = fmaxf(m, __shfl_xor_sync(0xffffffffu, m, off));

        dp = 0.f;
        for (int base = beg; base < end; base += 32) {
            int p = base + lane;
            float w = 0.f; int s = 0;
            if (p < end) {
                s = g_ssrc[p];
                float al = g_es[s] + edv;
                al = al > 0.f ? al : 0.2f * al;
                w = __expf(al - m);
                dp += w;
            }
            int cnt = min(32, end - base);
#pragma unroll 4
            for (int j = 0; j < cnt; j++) {
                float wj = __shfl_sync(0xffffffffu, w, j);
                int   sj = __shfl_sync(0xffffffffu, s, j);
                if (V == 4) {
                    float4 xv = *(const float4*)&g_xp[sj * C + lane * 4];
                    acc[0] += wj * xv.x; acc[1] += wj * xv.y;
                    acc[2] += wj * xv.z; acc[3] += wj * xv.w;
                } else {
                    float2 xv = *(const float2*)&g_xp[sj * C + lane * 2];
                    acc[0] += wj * xv.x; acc[1] += wj * xv.y;
                }
            }
        }
#pragma unroll
        for (int off = 16; off; off >>= 1) dp += __shfl_xor_sync(0xffffffffu, dp, off);
    }

    float inv = 1.f / dp;
    if (V == 4) {
        float4 b4 = *(const float4*)&bias[lane * 4];
        float4 o = make_float4(acc[0] * inv + b4.x, acc[1] * inv + b4.y,
                               acc[2] * inv + b4.z, acc[3] * inv + b4.w);
        *(float4*)&outp[node * C + lane * 4] = o;
    } else {
        float2 b2 = *(const float2*)&bias[lane * 2];
        float2 o = make_float2(acc[0] * inv + b2.x, acc[1] * inv + b2.y);
        *(float2*)&outp[node * C + lane * 2] = o;
    }
}

// ---------------- BatchNorm stats ----------------
__global__ void k_zero_stats() {
    int i = threadIdx.x;
    if (i < 2 * DHx) g_stats[i] = 0.f;
}
__global__ void k_bnstats(int n) {
    int c = threadIdx.x;
    float s = 0.f, sq = 0.f;
    for (int r = blockIdx.x; r < n; r += gridDim.x) {
        float v = g_h[r * 128 + c];
        s += v; sq += v * v;
    }
    atomicAdd(&g_stats[c], s);
    atomicAdd(&g_stats[128 + c], sq);
}
__global__ void k_bnparams(const float* __restrict__ g, const float* __restrict__ be, int n) {
    int c = threadIdx.x;
    float inv_n = 1.f / (float)n;
    float m = g_stats[c] * inv_n;
    float v = g_stats[128 + c] * inv_n - m * m;
    float scv = g[c] * rsqrtf(v + 1e-5f);
    g_scale[c] = scv;
    g_shift[c] = be[c] - m * scv;
}

// ---------------- pooling ----------------
__global__ void k_zero_pool(float* __restrict__ o) {
    int i = blockIdx.x * blockDim.x + threadIdx.x;
    if (i < NGx * DOUTx) o[i] = 0.f;
}
__global__ void k_pool(const float* __restrict__ gp, const float* __restrict__ hn,
                       float* __restrict__ outp, int n) {
    __shared__ float gpt[32][129];
    __shared__ float hnt[32][65];
    int tid = threadIdx.x;
    int tn = (tid & 15) * 4;
    int tm = (tid >> 4) * 8;
    float acc[8][4];
#pragma unroll
    for (int a = 0; a < 8; a++)
#pragma unroll
        for (int b = 0; b < 4; b++) acc[a][b] = 0.f;

    int kpb  = (n + gridDim.x - 1) / gridDim.x;
    int kbeg = blockIdx.x * kpb;
    int kend = min(n, kbeg + kpb);

    for (int k0 = kbeg; k0 < kend; k0 += 32) {
        int kt = min(32, kend - k0);
        for (int l = tid; l < 128 * 32; l += 256) {
            int m = l >> 5, kk = l & 31;
            gpt[kk][m] = (kk < kt) ? gp[m * n + k0 + kk] : 0.f;
        }
        for (int l = tid; l < 32 * 64; l += 256) {
            int kk = l >> 6, cc = l & 63;
            hnt[kk][cc] = (kk < kt) ? hn[(k0 + kk) * 64 + cc] : 0.f;
        }
        __syncthreads();
#pragma unroll 4
        for (int kk = 0; kk < 32; kk++) {
            float h0 = hnt[kk][tn + 0], h1 = hnt[kk][tn + 1];
            float h2 = hnt[kk][tn + 2], h3 = hnt[kk][tn + 3];
#pragma unroll
            for (int a = 0; a < 8; a++) {
                float g = gpt[kk][tm + a];
                acc[a][0] += g * h0;
                acc[a][1] += g * h1;
                acc[a][2] += g * h2;
                acc[a][3] += g * h3;
            }
        }
        __syncthreads();
    }
#pragma unroll
    for (int a = 0; a < 8; a++)
#pragma unroll
        for (int b = 0; b < 4; b++)
            atomicAdd(&outp[(tm + a) * 64 + tn + b], acc[a][b]);
}

// ---------------- launch ----------------
extern "C" void kernel_launch(void* const* d_in, const int* in_sizes, int n_in,
                              void* d_out, int out_size) {
    const float* x   = (const float*)d_in[0];
    const void*  ei  = (const void*)d_in[1];
    const float* gp  = (const float*)d_in[2];
    const float* W1  = (const float*)d_in[3];
    const float* as1 = (const float*)d_in[4];
    const float* ad1 = (const float*)d_in[5];
    const float* b1  = (const float*)d_in[6];
    const float* g1  = (const float*)d_in[7];
    const float* be1 = (const float*)d_in[8];
    const float* W2  = (const float*)d_in[9];
    const float* as2 = (const float*)d_in[10];
    const float* ad2 = (const float*)d_in[11];
    const float* b2  = (const float*)d_in[12];
    const float* g2  = (const float*)d_in[13];
    const float* be2 = (const float*)d_in[14];
    const float* W3  = (const float*)d_in[15];
    const float* as3 = (const float*)d_in[16];
    const float* ad3 = (const float*)d_in[17];
    const float* b3  = (const float*)d_in[18];

    float* out       = (float*)d_out;
    float* out_pool  = out;                    // [128,64]
    float* out_nodes = out + NGx * DOUTx;      // [50000,64]

    const int T = 256;
    const int SMA = 4096 + 64 * 576;           // 40960
    cudaFuncSetAttribute((const void*)k_gemm_mma<128, false>, cudaFuncAttributeMaxDynamicSharedMemorySize, SMA);
    cudaFuncSetAttribute((const void*)k_gemm_mma<128, true>,  cudaFuncAttributeMaxDynamicSharedMemorySize, SMA);
    cudaFuncSetAttribute((const void*)k_gemm_mma<64, true>,   cudaFuncAttributeMaxDynamicSharedMemorySize, SMA);

    int gemm_blocks = (NN + 63) / 64;          // 782
    int warp_blocks = (NN * 32 + T - 1) / T;

    // keep GEMM-1 at launch index 3 (ncu's profiled slot)
    k_detect<<<1, 256>>>((const unsigned int*)ei);
    k_zero_cnt<<<(NN + T - 1) / T, T>>>();
    k_prepw<128><<<16, 256>>>(W1);
    k_gemm_mma<128, false><<<gemm_blocks, 256, SMA>>>(x, as1, ad1, NN);   // <- profiled

    // CSR build
    k_hist<<<(ETOT + T - 1) / T, T>>>(ei);
    k_scan1<<<49, 1024>>>();
    k_scan2<<<1, 64>>>();
    k_scan3<<<49, 1024>>>();
    k_scatter<<<(ETOT + T - 1) / T, T>>>(ei);

    // ---- Layer 1 agg + BN ----
    k_agg<128><<<warp_blocks, T>>>(b1, nullptr);
    k_zero_stats<<<1, 256>>>();
    k_bnstats<<<512, 128>>>(NN);
    k_bnparams<<<1, 128>>>(g1, be1, NN);

    // ---- Layer 2 ----
    k_prepw<128><<<16, 256>>>(W2);
    k_gemm_mma<128, true><<<gemm_blocks, 256, SMA>>>(nullptr, as2, ad2, NN);
    k_agg<128><<<warp_blocks, T>>>(b2, nullptr);
    k_zero_stats<<<1, 256>>>();
    k_bnstats<<<512, 128>>>(NN);
    k_bnparams<<<1, 128>>>(g2, be2, NN);

    // ---- Layer 3 ----
    k_prepw<64><<<8, 256>>>(W3);
    k_gemm_mma<64, true><<<gemm_blocks, 256, SMA>>>(nullptr, as3, ad3, NN);
    k_agg<64><<<warp_blocks, T>>>(b3, out_nodes);

    // ---- pooling (atomics straight into d_out) ----
    k_zero_pool<<<(NGx * DOUTx + T - 1) / T, T>>>(out_pool);
    k_pool<<<128, 256>>>(gp, out_nodes, out_pool, NN);
}

// round 10
// speedup vs baseline: 2.0367x; 1.0359x over previous
#include <cuda_runtime.h>
#include <cuda_bf16.h>
#include <cstdint>

#define NN   50000
#define EE   800000
#define ETOT (EE + NN)
#define DHx  128
#define DOUTx 64
#define NGx  128

// ---------------- device scratch ----------------
__device__ int   g_is64;
__device__ int   g_cnt[NN];
__device__ int   g_btot[64];
__device__ int   g_boff[64];
__device__ int   g_rowptr[NN + 1];
__device__ int   g_cur[NN];
__device__ int   g_ssrc[ETOT];
__device__ float g_xp[NN * DHx];
__device__ float g_h [NN * DHx];
__device__ float g_es[NN];
__device__ float g_ed[NN];
__device__ float g_bsp[512 * 256];   // bnstats per-block partials
__device__ float g_scale[DHx];
__device__ float g_shift[DHx];
__device__ uint4 g_bpk[4096];        // fragment-packed W^T hi/lo

__device__ __forceinline__ uint32_t pack_bf2(float a, float b) {
    __nv_bfloat162 t = __floats2bfloat162_rn(a, b);
    return *(uint32_t*)&t;
}

__device__ __forceinline__ void mma_bf16(float* c, uint32_t a0, uint32_t a1, uint32_t a2,
                                         uint32_t a3, uint32_t b0, uint32_t b1) {
    asm volatile(
        "mma.sync.aligned.m16n8k16.row.col.f32.bf16.bf16.f32 "
        "{%0,%1,%2,%3},{%4,%5,%6,%7},{%8,%9},{%0,%1,%2,%3};"
        : "+f"(c[0]), "+f"(c[1]), "+f"(c[2]), "+f"(c[3])
        : "r"(a0), "r"(a1), "r"(a2), "r"(a3), "r"(b0), "r"(b1));
}

__device__ __forceinline__ int edge_at(const void* ei, int idx) {
    int v;
    if (g_is64) v = (int)((const long long*)ei)[idx];
    else        v = ((const int*)ei)[idx];
    v = v < 0 ? 0 : (v >= NN ? NN - 1 : v);
    return v;
}

// W prep body: transpose + bf16 hi/lo split, fragment-packed
template <int NOUT>
__device__ __forceinline__ void prepw_body(const float* __restrict__ W, int i) {
    if (i >= NOUT * 32) return;
    int n = i >> 5, ks = (i >> 2) & 7, tg = i & 3;
    int ka = ks * 16 + tg * 2;
    int kb = ka + 8;
    float w00 = W[ka * NOUT + n],       w01 = W[(ka + 1) * NOUT + n];
    float w10 = W[kb * NOUT + n],       w11 = W[(kb + 1) * NOUT + n];
    float h00 = __bfloat162float(__float2bfloat16_rn(w00));
    float h01 = __bfloat162float(__float2bfloat16_rn(w01));
    float h10 = __bfloat162float(__float2bfloat16_rn(w10));
    float h11 = __bfloat162float(__float2bfloat16_rn(w11));
    uint4 v;
    v.x = pack_bf2(w00, w01);
    v.y = pack_bf2(w10, w11);
    v.z = pack_bf2(w00 - h00, w01 - h01);
    v.w = pack_bf2(w10 - h10, w11 - h11);
    g_bpk[i] = v;
}

// ---------------- merged setup: detect + zero_cnt + prepw(W1) + zero_pool ----------------
// grid: [0]=detect, [1..196]=zero_cnt, [197..212]=prepw, [213..244]=zero_pool
__global__ void k_misc1(const unsigned int* __restrict__ ei_raw,
                        const float* __restrict__ W1, float* __restrict__ out_pool) {
    int b = blockIdx.x, t = threadIdx.x;
    if (b == 0) {
        __shared__ unsigned int sh[256];
        unsigned int v = 0;
        for (int i = t; i < 1024; i += 256) v |= ei_raw[2 * i + 1];
        sh[t] = v;
        __syncthreads();
        for (int off = 128; off; off >>= 1) {
            if (t < off) sh[t] |= sh[t + off];
            __syncthreads();
        }
        if (t == 0) g_is64 = (sh[0] == 0) ? 1 : 0;
    } else if (b <= 196) {
        int i = (b - 1) * 256 + t;
        if (i < NN) g_cnt[i] = 0;
    } else if (b <= 212) {
        prepw_body<128>(W1, (b - 197) * 256 + t);
    } else {
        int i = (b - 213) * 256 + t;
        if (i < NGx * DOUTx) out_pool[i] = 0.f;
    }
}

// ---------------- CSR build ----------------
__global__ void k_hist(const void* __restrict__ ei) {
    int e = blockIdx.x * blockDim.x + threadIdx.x;
    if (e >= ETOT) return;
    int dst = (e < EE) ? edge_at(ei, EE + e) : (e - EE);
    atomicAdd(&g_cnt[dst], 1);
}
__global__ void k_scan1() {
    int t = threadIdx.x;
    int i = blockIdx.x * 1024 + t;
    int v = (i < NN) ? g_cnt[i] : 0;
    __shared__ int sh[1024];
    sh[t] = v;
    __syncthreads();
    for (int off = 1; off < 1024; off <<= 1) {
        int a = (t >= off) ? sh[t - off] : 0;
        __syncthreads();
        sh[t] += a;
        __syncthreads();
    }
    if (i < NN) g_cnt[i] = sh[t] - v;
    if (t == 1023) g_btot[blockIdx.x] = sh[1023];
}
__global__ void k_scan2() {
    int t = threadIdx.x;
    int v = (t < 49) ? g_btot[t] : 0;
    __shared__ int sh[64];
    sh[t] = v;
    __syncthreads();
    for (int off = 1; off < 64; off <<= 1) {
        int a = (t >= off) ? sh[t - off] : 0;
        __syncthreads();
        sh[t] += a;
        __syncthreads();
    }
    if (t < 49) g_boff[t] = sh[t] - v;
}
__global__ void k_scan3() {
    int i = blockIdx.x * 1024 + threadIdx.x;
    if (i < NN) {
        int rp = g_cnt[i] + g_boff[blockIdx.x];
        g_rowptr[i] = rp;
        g_cur[i] = rp;
    }
    if (i == 0) g_rowptr[NN] = ETOT;
}
__global__ void k_scatter(const void* __restrict__ ei) {
    int e = blockIdx.x * blockDim.x + threadIdx.x;
    if (e >= ETOT) return;
    int s, d;
    if (e < EE) { s = edge_at(ei, e); d = edge_at(ei, EE + e); }
    else        { s = e - EE;         d = s; }
    int pos = atomicAdd(&g_cur[d], 1);
    g_ssrc[pos] = s;
}

// ---------------- warp-MMA GEMM: 64 x NOUT tile, K=128, 3-term bf16 split --------
template <int NOUT, bool BN>
__global__ void __launch_bounds__(256, 3) k_gemm_mma(const float* __restrict__ A,
                                                     const float* __restrict__ asv,
                                                     const float* __restrict__ adv, int n) {
    extern __shared__ char smem[];
    const float* __restrict__ Ap = BN ? (const float*)g_h : A;
    constexpr int RSTR = 576;
    float* sas = (float*)(smem);
    float* sad = (float*)(smem + 512);
    float* sc  = (float*)(smem + 1024);
    float* sf  = (float*)(smem + 1536);
    float* esp = (float*)(smem + 2048);
    float* edp = (float*)(smem + 3072);
    char*  ap  = smem + 4096;

    int tid = threadIdx.x, wid = tid >> 5, lane = tid & 31;
    int r0 = blockIdx.x * 64;

    if (tid < NOUT) { sas[tid] = asv[tid]; sad[tid] = adv[tid]; }
    if (BN && tid < 128) { sc[tid] = g_scale[tid]; sf[tid] = g_shift[tid]; }
    if (BN) __syncthreads();

    for (int l = tid; l < 64 * 32; l += 256) {
        int row = l >> 5, ks = (l >> 2) & 7, tg = l & 3;
        int ka = ks * 16 + tg * 2;
        int kb = ka + 8;
        float a0 = 0.f, a1 = 0.f, b0 = 0.f, b1 = 0.f;
        if (r0 + row < n) {
            float2 t = *(const float2*)&Ap[(r0 + row) * 128 + ka];
            a0 = t.x; a1 = t.y;
            float2 u = *(const float2*)&Ap[(r0 + row) * 128 + kb];
            b0 = u.x; b1 = u.y;
        }
        if (BN) {
            a0 = fmaxf(a0 * sc[ka] + sf[ka], 0.f);
            a1 = fmaxf(a1 * sc[ka + 1] + sf[ka + 1], 0.f);
            b0 = fmaxf(b0 * sc[kb] + sf[kb], 0.f);
            b1 = fmaxf(b1 * sc[kb + 1] + sf[kb + 1], 0.f);
        }
        float h0 = __bfloat162float(__float2bfloat16_rn(a0));
        float h1 = __bfloat162float(__float2bfloat16_rn(a1));
        float h2 = __bfloat162float(__float2bfloat16_rn(b0));
        float h3 = __bfloat162float(__float2bfloat16_rn(b1));
        uint4 v;
        v.x = pack_bf2(a0, a1);
        v.y = pack_bf2(b0, b1);
        v.z = pack_bf2(a0 - h0, a1 - h1);
        v.w = pack_bf2(b0 - h2, b1 - h3);
        *(uint4*)(ap + row * RSTR + ks * 64 + tg * 16) = v;
    }
    __syncthreads();

    constexpr int WN = (NOUT == 128) ? 32 : 16;
    constexpr int NA = WN / 8;
    int wm = (wid & 1) * 32;
    int wn = (wid >> 1) * WN;
    int gq = lane >> 2, tg = lane & 3, t2 = tg * 2;

    float acc[2][NA][4];
#pragma unroll
    for (int i = 0; i < 2; i++)
#pragma unroll
        for (int j = 0; j < NA; j++)
#pragma unroll
            for (int q = 0; q < 4; q++) acc[i][j][q] = 0.f;

#pragma unroll
    for (int ks = 0; ks < 8; ks++) {
        uint32_t fbh[NA][2], fbl[NA][2];
#pragma unroll
        for (int j = 0; j < NA; j++) {
            uint4 bv = g_bpk[(wn + j * 8 + gq) * 32 + ks * 4 + tg];
            fbh[j][0] = bv.x; fbh[j][1] = bv.y;
            fbl[j][0] = bv.z; fbl[j][1] = bv.w;
        }
#pragma unroll
        for (int i = 0; i < 2; i++) {
            int rl = wm + i * 16 + gq;
            uint4 av = *(uint4*)(ap + rl * RSTR + ks * 64 + tg * 16);
            uint4 aw = *(uint4*)(ap + (rl + 8) * RSTR + ks * 64 + tg * 16);
#pragma unroll
            for (int j = 0; j < NA; j++) {
                mma_bf16(acc[i][j], av.x, aw.x, av.y, aw.y, fbh[j][0], fbh[j][1]);
                mma_bf16(acc[i][j], av.x, aw.x, av.y, aw.y, fbl[j][0], fbl[j][1]);
                mma_bf16(acc[i][j], av.z, aw.z, av.w, aw.w, fbh[j][0], fbh[j][1]);
            }
        }
    }

    int wng = wid >> 1;
#pragma unroll
    for (int i = 0; i < 2; i++) {
        int rl = r0 + wm + i * 16 + gq;
        int rh = rl + 8;
        float psl = 0.f, pdl = 0.f, psh = 0.f, pdh = 0.f;
#pragma unroll
        for (int j = 0; j < NA; j++) {
            int c0 = wn + j * 8 + t2;
            if (rl < n) *(float2*)&g_xp[rl * NOUT + c0] = make_float2(acc[i][j][0], acc[i][j][1]);
            if (rh < n) *(float2*)&g_xp[rh * NOUT + c0] = make_float2(acc[i][j][2], acc[i][j][3]);
            float s0 = sas[c0], s1 = sas[c0 + 1], d0 = sad[c0], d1 = sad[c0 + 1];
            psl += acc[i][j][0] * s0 + acc[i][j][1] * s1;
            pdl += acc[i][j][0] * d0 + acc[i][j][1] * d1;
            psh += acc[i][j][2] * s0 + acc[i][j][3] * s1;
            pdh += acc[i][j][2] * d0 + acc[i][j][3] * d1;
        }
#pragma unroll
        for (int off = 1; off < 4; off <<= 1) {
            psl += __shfl_xor_sync(0xffffffffu, psl, off);
            pdl += __shfl_xor_sync(0xffffffffu, pdl, off);
            psh += __shfl_xor_sync(0xffffffffu, psh, off);
            pdh += __shfl_xor_sync(0xffffffffu, pdh, off);
        }
        if ((lane & 3) == 0) {
            int rowl = wm + i * 16 + gq;
            esp[wng * 64 + rowl] = psl;       edp[wng * 64 + rowl] = pdl;
            esp[wng * 64 + rowl + 8] = psh;   edp[wng * 64 + rowl + 8] = pdh;
        }
    }
    __syncthreads();
    if (tid < 64) {
        int r = r0 + tid;
        if (r < n) {
            g_es[r] = esp[tid] + esp[64 + tid] + esp[128 + tid] + esp[192 + tid];
            g_ed[r] = edp[tid] + edp[64 + tid] + edp[128 + tid] + edp[192 + tid];
        }
    }
}

// ---------------- GAT aggregation: one WARP per destination node ----------------
template <int C>
__global__ void k_agg(const float* __restrict__ bias, float* __restrict__ out) {
    float* __restrict__ outp = out ? out : (float*)g_h;
    int node = (blockIdx.x * blockDim.x + threadIdx.x) >> 5;
    int lane = threadIdx.x & 31;
    if (node >= NN) return;
    int beg = g_rowptr[node], end = g_rowptr[node + 1];
    int deg = end - beg;
    float edv = g_ed[node];

    constexpr int V = C / 32;
    float acc[V];
#pragma unroll
    for (int v = 0; v < V; v++) acc[v] = 0.f;
    float dp;

    if (deg <= 32) {
        int p = beg + lane;
        int s = 0;
        float al = -3.4e38f;
        if (p < end) {
            s = g_ssrc[p];
            float t = g_es[s] + edv;
            al = t > 0.f ? t : 0.2f * t;
        }
        float m = al;
#pragma unroll
        for (int off = 16; off; off >>= 1) m = fmaxf(m, __shfl_xor_sync(0xffffffffu, m, off));
        float w = (p < end) ? __expf(al - m) : 0.f;
        dp = w;
#pragma unroll
        for (int off = 16; off; off >>= 1) dp += __shfl_xor_sync(0xffffffffu, dp, off);

#pragma unroll 8
        for (int j = 0; j < deg; j++) {
            float wj = __shfl_sync(0xffffffffu, w, j);
            int   sj = __shfl_sync(0xffffffffu, s, j);
            if (V == 4) {
                float4 xv = *(const float4*)&g_xp[sj * C + lane * 4];
                acc[0] += wj * xv.x; acc[1] += wj * xv.y;
                acc[2] += wj * xv.z; acc[3] += wj * xv.w;
            } else {
                float2 xv = *(const float2*)&g_xp[sj * C + lane * 2];
                acc[0] += wj * xv.x; acc[1] += wj * xv.y;
            }
        }
    } else {
        float m = -3.4e38f;
        for (int p = beg + lane; p < end; p += 32) {
            float al = g_es[g_ssrc[p]] + edv;
            al = al > 0.f ? al : 0.2f * al;
            m = fmaxf(m, al);
        }
#pragma unroll
        for (int off = 16; off; off >>= 1) m = fmaxf(m, __shfl_xor_sync(0xffffffffu, m, off));

        dp = 0.f;
        for (int base = beg; base < end; base += 32) {
            int p = base + lane;
            float w = 0.f; int s = 0;
            if (p < end) {
                s = g_ssrc[p];
                float al = g_es[s] + edv;
                al = al > 0.f ? al : 0.2f * al;
                w = __expf(al - m);
                dp += w;
            }
            int cnt = min(32, end - base);
#pragma unroll 4
            for (int j = 0; j < cnt; j++) {
                float wj = __shfl_sync(0xffffffffu, w, j);
                int   sj = __shfl_sync(0xffffffffu, s, j);
                if (V == 4) {
                    float4 xv = *(const float4*)&g_xp[sj * C + lane * 4];
                    acc[0] += wj * xv.x; acc[1] += wj * xv.y;
                    acc[2] += wj * xv.z; acc[3] += wj * xv.w;
                } else {
                    float2 xv = *(const float2*)&g_xp[sj * C + lane * 2];
                    acc[0] += wj * xv.x; acc[1] += wj * xv.y;
                }
            }
        }
#pragma unroll
        for (int off = 16; off; off >>= 1) dp += __shfl_xor_sync(0xffffffffu, dp, off);
    }

    float inv = 1.f / dp;
    if (V == 4) {
        float4 b4 = *(const float4*)&bias[lane * 4];
        float4 o = make_float4(acc[0] * inv + b4.x, acc[1] * inv + b4.y,
                               acc[2] * inv + b4.z, acc[3] * inv + b4.w);
        *(float4*)&outp[node * C + lane * 4] = o;
    } else {
        float2 b2 = *(const float2*)&bias[lane * 2];
        float2 o = make_float2(acc[0] * inv + b2.x, acc[1] * inv + b2.y);
        *(float2*)&outp[node * C + lane * 2] = o;
    }
}

// ---------------- BatchNorm stats: per-block partials (no atomics, no zeroing) ------
__global__ void k_bnstats(int n) {
    int c = threadIdx.x;     // 128
    float s = 0.f, sq = 0.f;
    for (int r = blockIdx.x; r < n; r += 512) {
        float v = g_h[r * 128 + c];
        s += v; sq += v * v;
    }
    g_bsp[blockIdx.x * 256 + c] = s;
    g_bsp[blockIdx.x * 256 + 128 + c] = sq;
}

// BN params (block 0) + next layer's W prep (blocks 1..)
template <int NOUT_NEXT>
__global__ void k_bnparams_prepw(const float* __restrict__ g, const float* __restrict__ be,
                                 const float* __restrict__ Wn, int n) {
    if (blockIdx.x == 0) {
        int c = threadIdx.x;
        if (c < 128) {
            float s = 0.f, sq = 0.f;
            for (int b = 0; b < 512; b++) {
                s  += g_bsp[b * 256 + c];
                sq += g_bsp[b * 256 + 128 + c];
            }
            float inv_n = 1.f / (float)n;
            float m = s * inv_n;
            float v = sq * inv_n - m * m;
            float scv = g[c] * rsqrtf(v + 1e-5f);
            g_scale[c] = scv;
            g_shift[c] = be[c] - m * scv;
        }
    } else {
        prepw_body<NOUT_NEXT>(Wn, (blockIdx.x - 1) * 256 + threadIdx.x);
    }
}

// ---------------- pooling ----------------
__global__ void k_pool(const float* __restrict__ gp, const float* __restrict__ hn,
                       float* __restrict__ outp, int n) {
    __shared__ float gpt[32][129];
    __shared__ float hnt[32][65];
    int tid = threadIdx.x;
    int tn = (tid & 15) * 4;
    int tm = (tid >> 4) * 8;
    float acc[8][4];
#pragma unroll
    for (int a = 0; a < 8; a++)
#pragma unroll
        for (int b = 0; b < 4; b++) acc[a][b] = 0.f;

    int kpb  = (n + gridDim.x - 1) / gridDim.x;
    int kbeg = blockIdx.x * kpb;
    int kend = min(n, kbeg + kpb);

    for (int k0 = kbeg; k0 < kend; k0 += 32) {
        int kt = min(32, kend - k0);
        for (int l = tid; l < 128 * 32; l += 256) {
            int m = l >> 5, kk = l & 31;
            gpt[kk][m] = (kk < kt) ? gp[m * n + k0 + kk] : 0.f;
        }
        for (int l = tid; l < 32 * 64; l += 256) {
            int kk = l >> 6, cc = l & 63;
            hnt[kk][cc] = (kk < kt) ? hn[(k0 + kk) * 64 + cc] : 0.f;
        }
        __syncthreads();
#pragma unroll 4
        for (int kk = 0; kk < 32; kk++) {
            float h0 = hnt[kk][tn + 0], h1 = hnt[kk][tn + 1];
            float h2 = hnt[kk][tn + 2], h3 = hnt[kk][tn + 3];
#pragma unroll
            for (int a = 0; a < 8; a++) {
                float g = gpt[kk][tm + a];
                acc[a][0] += g * h0;
                acc[a][1] += g * h1;
                acc[a][2] += g * h2;
                acc[a][3] += g * h3;
            }
        }
        __syncthreads();
    }
#pragma unroll
    for (int a = 0; a < 8; a++)
#pragma unroll
        for (int b = 0; b < 4; b++)
            atomicAdd(&outp[(tm + a) * 64 + tn + b], acc[a][b]);
}

// ---------------- launch ----------------
extern "C" void kernel_launch(void* const* d_in, const int* in_sizes, int n_in,
                              void* d_out, int out_size) {
    const float* x   = (const float*)d_in[0];
    const void*  ei  = (const void*)d_in[1];
    const float* gp  = (const float*)d_in[2];
    const float* W1  = (const float*)d_in[3];
    const float* as1 = (const float*)d_in[4];
    const float* ad1 = (const float*)d_in[5];
    const float* b1  = (const float*)d_in[6];
    const float* g1  = (const float*)d_in[7];
    const float* be1 = (const float*)d_in[8];
    const float* W2  = (const float*)d_in[9];
    const float* as2 = (const float*)d_in[10];
    const float* ad2 = (const float*)d_in[11];
    const float* b2  = (const float*)d_in[12];
    const float* g2  = (const float*)d_in[13];
    const float* be2 = (const float*)d_in[14];
    const float* W3  = (const float*)d_in[15];
    const float* as3 = (const float*)d_in[16];
    const float* ad3 = (const float*)d_in[17];
    const float* b3  = (const float*)d_in[18];

    float* out       = (float*)d_out;
    float* out_pool  = out;                    // [128,64]
    float* out_nodes = out + NGx * DOUTx;      // [50000,64]

    const int T = 256;
    const int SMA = 4096 + 64 * 576;           // 40960 (< 48K default)

    int gemm_blocks = (NN + 63) / 64;          // 782
    int warp_blocks = (NN * 32 + T - 1) / T;

    // 1: merged setup (detect + zero_cnt + prepw W1 + zero_pool)
    k_misc1<<<245, 256>>>((const unsigned int*)ei, W1, out_pool);
    // 2-3: CSR start
    k_hist<<<(ETOT + T - 1) / T, T>>>(ei);
    k_scan1<<<49, 1024>>>();
    // 4: GEMM-1 (ncu's profiled slot)
    k_gemm_mma<128, false><<<gemm_blocks, 256, SMA>>>(x, as1, ad1, NN);
    // 5-7: CSR finish
    k_scan2<<<1, 64>>>();
    k_scan3<<<49, 1024>>>();
    k_scatter<<<(ETOT + T - 1) / T, T>>>(ei);

    // ---- Layer 1 agg + BN stats ----
    k_agg<128><<<warp_blocks, T>>>(b1, nullptr);
    k_bnstats<<<512, 128>>>(NN);
    k_bnparams_prepw<128><<<17, 256>>>(g1, be1, W2, NN);

    // ---- Layer 2 ----
    k_gemm_mma<128, true><<<gemm_blocks, 256, SMA>>>(nullptr, as2, ad2, NN);
    k_agg<128><<<warp_blocks, T>>>(b2, nullptr);
    k_bnstats<<<512, 128>>>(NN);
    k_bnparams_prepw<64><<<9, 256>>>(g2, be2, W3, NN);

    // ---- Layer 3 ----
    k_gemm_mma<64, true><<<gemm_blocks, 256, SMA>>>(nullptr, as3, ad3, NN);
    k_agg<64><<<warp_blocks, T>>>(b3, out_nodes);

    // ---- pooling (atomics straight into d_out, zeroed in k_misc1) ----
    k_pool<<<128, 256>>>(gp, out_nodes, out_pool, NN);
}